// round 2
// baseline (speedup 1.0000x reference)
#include <cuda_runtime.h>
#include <math.h>
#include <stdint.h>

#define Nn 50000
#define Ee 800000
#define Gg 512
#define EPS 1e-5f

// ------------------------- device scratch (static, no allocs) ---------------
__device__ float g_sum1[512], g_sumsq1[512], g_scale1[512], g_shift1[512];
__device__ __align__(16) float g_Wc2[16 * 512];
__device__ float g_bc2[16];
__device__ __align__(16) float g_z[(size_t)Nn * 48];
__device__ float g_sum2[48], g_sumsq2[48], g_scale2[48], g_shift2[48];
__device__ float g_Wp2[64 * 48], g_bp2[64];
__device__ __align__(16) float g_t[(size_t)Nn * 64];
__device__ __align__(16) float g_h[(size_t)Nn * 256];
__device__ __align__(16) float g_asrc[Nn * 4];
__device__ __align__(16) float g_adst[Nn * 4];
__device__ __align__(16) unsigned g_m[Nn * 4];
__device__ __align__(16) float g_mf[Nn * 4];
__device__ __align__(16) float g_s[Nn * 4];
__device__ __align__(16) float g_ex[(size_t)Ee * 4];
__device__ __align__(16) float g_agg[(size_t)Nn * 256];
__device__ float g_sum3[256], g_sumsq3[256], g_scale3[256], g_shift3[256];
__device__ float g_pooled[Gg * 256];
__device__ float g_cnt[Gg];

// ------------------------- helpers ------------------------------------------
__device__ __forceinline__ float warp_sum(float v) {
    #pragma unroll
    for (int off = 16; off; off >>= 1) v += __shfl_xor_sync(0xffffffffu, v, off);
    return v;
}

__device__ __forceinline__ unsigned fenc(float f) {
    unsigned u = __float_as_uint(f);
    return (u & 0x80000000u) ? ~u : (u | 0x80000000u);
}
__device__ __forceinline__ float fdec(unsigned u) {
    return (u & 0x80000000u) ? __uint_as_float(u ^ 0x80000000u) : __uint_as_float(~u);
}

__device__ __forceinline__ void red_add_v4(float* p, float a, float b, float c, float d) {
    asm volatile("red.global.add.v4.f32 [%0], {%1,%2,%3,%4};"
                 :: "l"(p), "f"(a), "f"(b), "f"(c), "f"(d) : "memory");
}

// ------------------------- init (per-launch reset; graph-replay safe) -------
__global__ void k_init() {
    long long i = (long long)blockIdx.x * blockDim.x + threadIdx.x;
    long long stride = (long long)gridDim.x * blockDim.x;
    for (long long j = i; j < (long long)Nn * 256; j += stride) g_agg[j] = 0.f;
    for (long long j = i; j < (long long)Nn * 4; j += stride) { g_m[j] = 0x007FFFFFu; g_s[j] = 0.f; }
    for (long long j = i; j < (long long)Gg * 256; j += stride) g_pooled[j] = 0.f;
    if (i < 512) { g_sum1[i] = 0.f; g_sumsq1[i] = 0.f; }
    if (i < 256) { g_sum3[i] = 0.f; g_sumsq3[i] = 0.f; }
    if (i < 48)  { g_sum2[i] = 0.f; g_sumsq2[i] = 0.f; }
    if (i < Gg)  g_cnt[i] = 0.f;
}

// ------------------------- bn1 stats over x[:, :512] ------------------------
__global__ void k_bn1_stats(const float* __restrict__ x) {
    int c = threadIdx.x;  // 512 threads
    float s = 0.f, q = 0.f;
    for (int r = blockIdx.x; r < Nn; r += gridDim.x) {
        float v = x[(size_t)r * 544 + c];
        s += v; q += v * v;
    }
    atomicAdd(&g_sum1[c], s);
    atomicAdd(&g_sumsq1[c], q);
}

// generic bn finalize: mode 0 -> bn1(512), 1 -> bn2(48), 2 -> bn3(256)
__global__ void k_fin(const float* __restrict__ g, const float* __restrict__ b,
                      int mode, int n, float invN) {
    int t = blockIdx.x * blockDim.x + threadIdx.x;
    if (t >= n) return;
    float *sum, *sq, *sc, *sh;
    if (mode == 0)      { sum = g_sum1; sq = g_sumsq1; sc = g_scale1; sh = g_shift1; }
    else if (mode == 1) { sum = g_sum2; sq = g_sumsq2; sc = g_scale2; sh = g_shift2; }
    else                { sum = g_sum3; sq = g_sumsq3; sc = g_scale3; sh = g_shift3; }
    float mean = sum[t] * invN;
    float var  = sq[t] * invN - mean * mean;
    float r = rsqrtf(var + EPS);
    float s = r * g[t];
    sc[t] = s;
    sh[t] = b[t] - mean * s;
}

// fold bn1 into Wc
__global__ void k_fold_wc(const float* __restrict__ Wc, const float* __restrict__ bc) {
    __shared__ float red[512];
    int o = blockIdx.x, t = threadIdx.x;
    float w = Wc[o * 512 + t];
    g_Wc2[o * 512 + t] = w * g_scale1[t];
    red[t] = w * g_shift1[t];
    __syncthreads();
    for (int s = 256; s; s >>= 1) { if (t < s) red[t] += red[t + s]; __syncthreads(); }
    if (t == 0) g_bc2[o] = bc[o] + red[0];
}

// fold bn2 into Wp
__global__ void k_fold_wp(const float* __restrict__ Wp, const float* __restrict__ bp) {
    __shared__ float red[64];
    int o = blockIdx.x, t = threadIdx.x;
    float p = 0.f;
    if (t < 48) {
        float w = Wp[o * 48 + t];
        g_Wp2[o * 48 + t] = w * g_scale2[t];
        p = w * g_shift2[t];
    }
    red[t] = p;
    __syncthreads();
    for (int s = 32; s; s >>= 1) { if (t < s) red[t] += red[t + s]; __syncthreads(); }
    if (t == 0) g_bp2[o] = bp[o] + red[0];
}

// ------------------------- per node: LN(f) + Wc2 matmul -> z, bn2 stats -----
__global__ void k_node_z(const float* __restrict__ x,
                         const float* __restrict__ ln_g, const float* __restrict__ ln_b) {
    __shared__ float sh_s[48], sh_q[48];
    int tid = threadIdx.x;
    if (tid < 48) { sh_s[tid] = 0.f; sh_q[tid] = 0.f; }
    __syncthreads();
    int w = tid >> 5, lane = tid & 31;
    int n = blockIdx.x * 8 + w;  // 6250 blocks x 8 warps = 50000 exactly
    const float* row = x + (size_t)n * 544;

    // layernorm on f = x[:, 512:544]
    float fv = row[512 + lane];
    float mu = warp_sum(fv) * (1.f / 32.f);
    float qq = warp_sum(fv * fv) * (1.f / 32.f);
    float fr = rsqrtf(qq - mu * mu + EPS);
    float fn = (fv - mu) * fr * ln_g[lane] + ln_b[lane];

    // x_cnn = bn1(x[:, :512]) @ Wc.T + bc, folded into Wc2/bc2
    float acc[16];
    #pragma unroll
    for (int o = 0; o < 16; o++) acc[o] = 0.f;
    #pragma unroll
    for (int i = 0; i < 16; i++) {
        int c = lane + 32 * i;
        float xv = row[c];
        #pragma unroll
        for (int o = 0; o < 16; o++) acc[o] += xv * g_Wc2[o * 512 + c];
    }
    float xc = 0.f;
    #pragma unroll
    for (int o = 0; o < 16; o++) {
        float v = warp_sum(acc[o]);
        if (lane == o) xc = v + g_bc2[o];
    }

    float* zr = g_z + (size_t)n * 48;
    if (lane < 16) zr[lane] = xc;
    zr[16 + lane] = fn;

    // bn2 stats
    if (lane < 16) { atomicAdd(&sh_s[lane], xc); atomicAdd(&sh_q[lane], xc * xc); }
    atomicAdd(&sh_s[16 + lane], fn);
    atomicAdd(&sh_q[16 + lane], fn * fn);
    __syncthreads();
    if (tid < 48) { atomicAdd(&g_sum2[tid], sh_s[tid]); atomicAdd(&g_sumsq2[tid], sh_q[tid]); }
}

// ------------------------- per node: t = relu(Wp2 z + bp2) ------------------
__global__ void k_node_t() {
    __shared__ float wp[64 * 49];
    __shared__ float zb[8][48];
    int tid = threadIdx.x;
    for (int i = tid; i < 64 * 48; i += 256) {
        int o = i / 48, k = i - o * 48;
        wp[o * 49 + k] = g_Wp2[i];
    }
    __syncthreads();
    int w = tid >> 5, lane = tid & 31;
    int n = blockIdx.x * 8 + w;
    const float* zr = g_z + (size_t)n * 48;
    zb[w][lane] = zr[lane];
    if (lane < 16) zb[w][32 + lane] = zr[32 + lane];
    __syncwarp();
    float t0 = g_bp2[lane], t1 = g_bp2[lane + 32];
    #pragma unroll
    for (int k = 0; k < 48; k++) {
        float zv = zb[w][k];
        t0 += wp[lane * 49 + k] * zv;
        t1 += wp[(lane + 32) * 49 + k] * zv;
    }
    g_t[(size_t)n * 64 + lane]      = fmaxf(t0, 0.f);
    g_t[(size_t)n * 64 + lane + 32] = fmaxf(t1, 0.f);
}

// ------------------------- GEMM: h = t @ Wg^T  (N x 64 x 256) ---------------
// block: 256 thr; tile 64 nodes x 64 outs; K=64. static smem, pad 68.
__global__ void k_gemm_h(const float* __restrict__ Wg) {
    __shared__ float tsh[64 * 68];
    __shared__ float wsh[64 * 68];
    int n0 = blockIdx.x * 64;
    int out0 = blockIdx.y * 64;
    int tid = threadIdx.x;

    for (int i = tid; i < 64 * 16; i += 256) {
        int r = i >> 4, c = (i & 15) << 2;
        float4 v = make_float4(0.f, 0.f, 0.f, 0.f);
        int n = n0 + r;
        if (n < Nn) v = *(const float4*)&g_t[(size_t)n * 64 + c];
        *(float4*)&tsh[r * 68 + c] = v;
        float4 wv = *(const float4*)&Wg[(size_t)(out0 + r) * 64 + c];
        *(float4*)&wsh[r * 68 + c] = wv;
    }
    __syncthreads();

    int tx = tid & 31, ty = tid >> 5;
    float acc[8][2];
    #pragma unroll
    for (int i = 0; i < 8; i++) { acc[i][0] = 0.f; acc[i][1] = 0.f; }

    #pragma unroll 4
    for (int k = 0; k < 64; k += 4) {
        float4 tv[8], wv[2];
        #pragma unroll
        for (int i = 0; i < 8; i++) tv[i] = *(float4*)&tsh[(ty * 8 + i) * 68 + k];
        wv[0] = *(float4*)&wsh[tx * 68 + k];
        wv[1] = *(float4*)&wsh[(tx + 32) * 68 + k];
        #pragma unroll
        for (int i = 0; i < 8; i++) {
            #pragma unroll
            for (int o = 0; o < 2; o++) {
                acc[i][o] += tv[i].x * wv[o].x;
                acc[i][o] += tv[i].y * wv[o].y;
                acc[i][o] += tv[i].z * wv[o].z;
                acc[i][o] += tv[i].w * wv[o].w;
            }
        }
    }
    #pragma unroll
    for (int i = 0; i < 8; i++) {
        int n = n0 + ty * 8 + i;
        if (n < Nn) {
            g_h[(size_t)n * 256 + out0 + tx]      = acc[i][0];
            g_h[(size_t)n * 256 + out0 + tx + 32] = acc[i][1];
        }
    }
}

// ------------------------- per node attention logits ------------------------
__global__ void k_att(const float* __restrict__ att_src, const float* __restrict__ att_dst) {
    int tid = threadIdx.x, w = tid >> 5, lane = tid & 31;
    int n = blockIdx.x * 8 + w;
    const float* hr = g_h + (size_t)n * 256;
    float ps[4] = {0.f, 0.f, 0.f, 0.f}, pd[4] = {0.f, 0.f, 0.f, 0.f};
    #pragma unroll
    for (int o = 0; o < 8; o++) {
        int out = o * 32 + lane;
        float hv = hr[out];
        int hd = o >> 1;
        ps[hd] += hv * att_src[out];
        pd[hd] += hv * att_dst[out];
    }
    #pragma unroll
    for (int hd = 0; hd < 4; hd++) {
        float vs = warp_sum(ps[hd]);
        float vd = warp_sum(pd[hd]);
        if (lane == 0) { g_asrc[n * 4 + hd] = vs; g_adst[n * 4 + hd] = vd; }
    }
}

// ------------------------- edge pass 1: segment max -------------------------
__global__ void k_edge_max(const int* __restrict__ ei) {
    int e = blockIdx.x * 256 + threadIdx.x;
    int si = ei[e], di = ei[Ee + e];
    float4 a = *(const float4*)&g_asrc[si * 4];
    float4 b = *(const float4*)&g_adst[di * 4];
    float v0 = a.x + b.x, v1 = a.y + b.y, v2 = a.z + b.z, v3 = a.w + b.w;
    v0 = v0 > 0.f ? v0 : 0.2f * v0;
    v1 = v1 > 0.f ? v1 : 0.2f * v1;
    v2 = v2 > 0.f ? v2 : 0.2f * v2;
    v3 = v3 > 0.f ? v3 : 0.2f * v3;
    unsigned* mp = &g_m[di * 4];
    atomicMax(mp + 0, fenc(v0));
    atomicMax(mp + 1, fenc(v1));
    atomicMax(mp + 2, fenc(v2));
    atomicMax(mp + 3, fenc(v3));
}

__global__ void k_fin_m() {
    int i = blockIdx.x * 256 + threadIdx.x;
    if (i >= Nn * 4) return;
    float f = fdec(g_m[i]);
    if (!isfinite(f)) f = 0.f;
    g_mf[i] = f;
}

// ------------------------- edge pass 2: exp + segment sum -------------------
__global__ void k_edge_sum(const int* __restrict__ ei) {
    int e = blockIdx.x * 256 + threadIdx.x;
    int si = ei[e], di = ei[Ee + e];
    float4 a = *(const float4*)&g_asrc[si * 4];
    float4 b = *(const float4*)&g_adst[di * 4];
    float4 m = *(const float4*)&g_mf[di * 4];
    float v0 = a.x + b.x, v1 = a.y + b.y, v2 = a.z + b.z, v3 = a.w + b.w;
    v0 = v0 > 0.f ? v0 : 0.2f * v0;
    v1 = v1 > 0.f ? v1 : 0.2f * v1;
    v2 = v2 > 0.f ? v2 : 0.2f * v2;
    v3 = v3 > 0.f ? v3 : 0.2f * v3;
    float e0 = expf(v0 - m.x), e1 = expf(v1 - m.y), e2 = expf(v2 - m.z), e3 = expf(v3 - m.w);
    *(float4*)&g_ex[(size_t)e * 4] = make_float4(e0, e1, e2, e3);
    red_add_v4(&g_s[di * 4], e0, e1, e2, e3);
}

// ------------------------- edge pass 3: weighted aggregation ----------------
// one warp per edge: lane covers 8 of 256 channels (head = lane>>3, constant).
__global__ void k_edge_agg(const int* __restrict__ ei) {
    int tid = threadIdx.x;
    int e = blockIdx.x * 8 + (tid >> 5);
    int lane = tid & 31;
    int si = __ldg(&ei[e]), di = __ldg(&ei[Ee + e]);
    float4 ex4 = *(const float4*)&g_ex[(size_t)e * 4];
    float4 s4  = *(const float4*)&g_s[di * 4];
    int hd = lane >> 3;
    float ex = hd == 0 ? ex4.x : hd == 1 ? ex4.y : hd == 2 ? ex4.z : ex4.w;
    float ss = hd == 0 ? s4.x  : hd == 1 ? s4.y  : hd == 2 ? s4.z  : s4.w;
    float al = ex / fmaxf(ss, 1e-16f);
    const float4* hrow = (const float4*)(g_h + (size_t)si * 256);
    float4 h0 = hrow[lane * 2], h1 = hrow[lane * 2 + 1];
    float* dst = g_agg + (size_t)di * 256 + lane * 8;
    red_add_v4(dst,     al * h0.x, al * h0.y, al * h0.z, al * h0.w);
    red_add_v4(dst + 4, al * h1.x, al * h1.y, al * h1.z, al * h1.w);
}

// ------------------------- bn3 stats -----------------------------------------
__global__ void k_bn3_stats() {
    int c = threadIdx.x;  // 256
    float s = 0.f, q = 0.f;
    for (int r = blockIdx.x; r < Nn; r += gridDim.x) {
        float v = g_agg[(size_t)r * 256 + c];
        s += v; q += v * v;
    }
    atomicAdd(&g_sum3[c], s);
    atomicAdd(&g_sumsq3[c], q);
}

// ------------------------- bn3 + elu + graph pooling -------------------------
__global__ void k_pool(const int* __restrict__ batch) {
    int n = blockIdx.x, c = threadIdx.x;
    int b = batch[n];
    float v = g_agg[(size_t)n * 256 + c] * g_scale3[c] + g_shift3[c];
    v = v > 0.f ? v : (expf(v) - 1.f);
    atomicAdd(&g_pooled[b * 256 + c], v);
    if (c == 0) atomicAdd(&g_cnt[b], 1.f);
}

// ------------------------- head MLP ------------------------------------------
__global__ void k_head(const float* __restrict__ W1, const float* __restrict__ b1,
                       const float* __restrict__ W2, const float* __restrict__ b2,
                       float* __restrict__ out) {
    __shared__ float p[256];
    __shared__ float hm[64];
    int g = blockIdx.x, t = threadIdx.x;
    float cnt = fmaxf(g_cnt[g], 1.f);
    p[t] = g_pooled[g * 256 + t] / cnt;
    __syncthreads();
    if (t < 64) {
        float a = b1[t];
        #pragma unroll 8
        for (int c = 0; c < 256; c++) a += p[c] * W1[t * 256 + c];
        hm[t] = fmaxf(a, 0.f);
    }
    __syncthreads();
    if (t < 2) {
        float a = b2[t];
        #pragma unroll
        for (int k = 0; k < 64; k++) a += hm[k] * W2[t * 64 + k];
        out[g * 2 + t] = a;
    }
}

// ------------------------- launch ---------------------------------------------
extern "C" void kernel_launch(void* const* d_in, const int* in_sizes, int n_in,
                              void* d_out, int out_size) {
    const float* x       = (const float*)d_in[0];
    const int*   ei      = (const int*)d_in[1];    // jax int64 -> int32 (x64 disabled)
    const int*   batch   = (const int*)d_in[2];
    const float* ln_g    = (const float*)d_in[3];
    const float* ln_b    = (const float*)d_in[4];
    const float* bn1_g   = (const float*)d_in[5];
    const float* bn1_b   = (const float*)d_in[6];
    const float* Wc      = (const float*)d_in[7];
    const float* bc      = (const float*)d_in[8];
    const float* bn2_g   = (const float*)d_in[9];
    const float* bn2_b   = (const float*)d_in[10];
    const float* Wp      = (const float*)d_in[11];
    const float* bp      = (const float*)d_in[12];
    const float* Wg      = (const float*)d_in[13];
    const float* att_src = (const float*)d_in[14];
    const float* att_dst = (const float*)d_in[15];
    // d_in[16] = bg : provably cancels under bn3 (pure mean shift) -> unused
    const float* bn3_g   = (const float*)d_in[17];
    const float* bn3_b   = (const float*)d_in[18];
    const float* W1      = (const float*)d_in[19];
    const float* b1      = (const float*)d_in[20];
    const float* W2      = (const float*)d_in[21];
    const float* b2      = (const float*)d_in[22];
    float* out = (float*)d_out;

    k_init<<<8192, 256>>>();
    k_bn1_stats<<<512, 512>>>(x);
    k_fin<<<2, 256>>>(bn1_g, bn1_b, 0, 512, 1.f / Nn);
    k_fold_wc<<<16, 512>>>(Wc, bc);
    k_node_z<<<6250, 256>>>(x, ln_g, ln_b);
    k_fin<<<1, 256>>>(bn2_g, bn2_b, 1, 48, 1.f / Nn);
    k_fold_wp<<<64, 64>>>(Wp, bp);
    k_node_t<<<6250, 256>>>();
    dim3 gh(782, 4);
    k_gemm_h<<<gh, 256>>>(Wg);
    k_att<<<6250, 256>>>(att_src, att_dst);
    k_edge_max<<<3125, 256>>>(ei);
    k_fin_m<<<(Nn * 4 + 255) / 256, 256>>>();
    k_edge_sum<<<3125, 256>>>(ei);
    k_edge_agg<<<100000, 256>>>(ei);
    k_bn3_stats<<<512, 256>>>();
    k_fin<<<1, 256>>>(bn3_g, bn3_b, 2, 256, 1.f / Nn);
    k_pool<<<Nn, 256>>>(batch);
    k_head<<<Gg, 256>>>(W1, b1, W2, b2, out);
}

// round 3
// speedup vs baseline: 1.1689x; 1.1689x over previous
#include <cuda_runtime.h>
#include <math.h>
#include <stdint.h>

#define Nn 50000
#define Ee 800000
#define Gg 512
#define EPS 1e-5f

// ------------------------- device scratch (static, no allocs) ---------------
__device__ float g_sum1[512], g_sumsq1[512], g_scale1[512], g_shift1[512];
__device__ __align__(16) float g_Wc2[16 * 512];
__device__ float g_bc2[16];
__device__ __align__(16) float g_z[(size_t)Nn * 48];
__device__ float g_sum2[48], g_sumsq2[48], g_scale2[48], g_shift2[48];
__device__ float g_Wp2[64 * 48], g_bp2[64];
__device__ __align__(16) float g_t[(size_t)Nn * 64];
__device__ float g_wsrc[4 * 64], g_wdst[4 * 64];
__device__ __align__(16) float g_asrc[Nn * 4];
__device__ __align__(16) float g_adst[Nn * 4];
__device__ int g_deg[Nn];
__device__ int g_rowptr[Nn + 1];
__device__ int g_cursor[Nn];
__device__ int g_col[Ee];
__device__ __align__(16) float g_aggt[(size_t)Nn * 256];   // per-head aggregated t
__device__ __align__(16) float g_out[(size_t)Nn * 256];    // aggt @ Wg^T (pre-bn3)
__device__ float g_sum3[256], g_sumsq3[256], g_scale3[256], g_shift3[256];
__device__ float g_pooled[Gg * 256];
__device__ float g_cnt[Gg];

// ------------------------- helpers ------------------------------------------
__device__ __forceinline__ float warp_sum(float v) {
    #pragma unroll
    for (int off = 16; off; off >>= 1) v += __shfl_xor_sync(0xffffffffu, v, off);
    return v;
}

// ------------------------- init (per-launch reset; graph-replay safe) -------
__global__ void k_init() {
    int i = blockIdx.x * blockDim.x + threadIdx.x;
    int stride = gridDim.x * blockDim.x;
    for (int j = i; j < Nn; j += stride) g_deg[j] = 0;
    for (int j = i; j < Gg * 256; j += stride) g_pooled[j] = 0.f;
    if (i < 512) { g_sum1[i] = 0.f; g_sumsq1[i] = 0.f; }
    if (i < 256) { g_sum3[i] = 0.f; g_sumsq3[i] = 0.f; }
    if (i < 48)  { g_sum2[i] = 0.f; g_sumsq2[i] = 0.f; }
    if (i < Gg)  g_cnt[i] = 0.f;
}

// ------------------------- bn1 stats over x[:, :512] ------------------------
__global__ void k_bn1_stats(const float* __restrict__ x) {
    int c = threadIdx.x;  // 512 threads
    float s = 0.f, q = 0.f;
    for (int r = blockIdx.x; r < Nn; r += gridDim.x) {
        float v = x[(size_t)r * 544 + c];
        s += v; q += v * v;
    }
    atomicAdd(&g_sum1[c], s);
    atomicAdd(&g_sumsq1[c], q);
}

// generic bn finalize: mode 0 -> bn1(512), 1 -> bn2(48), 2 -> bn3(256)
__global__ void k_fin(const float* __restrict__ g, const float* __restrict__ b,
                      int mode, int n, float invN) {
    int t = blockIdx.x * blockDim.x + threadIdx.x;
    if (t >= n) return;
    float *sum, *sq, *sc, *sh;
    if (mode == 0)      { sum = g_sum1; sq = g_sumsq1; sc = g_scale1; sh = g_shift1; }
    else if (mode == 1) { sum = g_sum2; sq = g_sumsq2; sc = g_scale2; sh = g_shift2; }
    else                { sum = g_sum3; sq = g_sumsq3; sc = g_scale3; sh = g_shift3; }
    float mean = sum[t] * invN;
    float var  = sq[t] * invN - mean * mean;
    float r = rsqrtf(var + EPS);
    float s = r * g[t];
    sc[t] = s;
    sh[t] = b[t] - mean * s;
}

// fold bn1 into Wc
__global__ void k_fold_wc(const float* __restrict__ Wc, const float* __restrict__ bc) {
    __shared__ float red[512];
    int o = blockIdx.x, t = threadIdx.x;
    float w = Wc[o * 512 + t];
    g_Wc2[o * 512 + t] = w * g_scale1[t];
    red[t] = w * g_shift1[t];
    __syncthreads();
    for (int s = 256; s; s >>= 1) { if (t < s) red[t] += red[t + s]; __syncthreads(); }
    if (t == 0) g_bc2[o] = bc[o] + red[0];
}

// fold bn2 into Wp
__global__ void k_fold_wp(const float* __restrict__ Wp, const float* __restrict__ bp) {
    __shared__ float red[64];
    int o = blockIdx.x, t = threadIdx.x;
    float p = 0.f;
    if (t < 48) {
        float w = Wp[o * 48 + t];
        g_Wp2[o * 48 + t] = w * g_scale2[t];
        p = w * g_shift2[t];
    }
    red[t] = p;
    __syncthreads();
    for (int s = 32; s; s >>= 1) { if (t < s) red[t] += red[t + s]; __syncthreads(); }
    if (t == 0) g_bp2[o] = bp[o] + red[0];
}

// fold attention vectors through Wg: wsrc[hd,k] = sum_j att_src[hd,j]*Wg[hd*64+j,k]
__global__ void k_fold_att(const float* __restrict__ Wg,
                           const float* __restrict__ att_src,
                           const float* __restrict__ att_dst) {
    __shared__ float as[64], ad[64];
    int hd = blockIdx.x, k = threadIdx.x;
    as[k] = att_src[hd * 64 + k];
    ad[k] = att_dst[hd * 64 + k];
    __syncthreads();
    float s = 0.f, d = 0.f;
    #pragma unroll 8
    for (int j = 0; j < 64; j++) {
        float w = Wg[(size_t)(hd * 64 + j) * 64 + k];
        s += as[j] * w;
        d += ad[j] * w;
    }
    g_wsrc[hd * 64 + k] = s;
    g_wdst[hd * 64 + k] = d;
}

// ------------------------- per node: LN(f) + Wc2 matmul -> z, bn2 stats -----
__global__ void k_node_z(const float* __restrict__ x,
                         const float* __restrict__ ln_g, const float* __restrict__ ln_b) {
    __shared__ float sh_s[48], sh_q[48];
    int tid = threadIdx.x;
    if (tid < 48) { sh_s[tid] = 0.f; sh_q[tid] = 0.f; }
    __syncthreads();
    int w = tid >> 5, lane = tid & 31;
    int n = blockIdx.x * 8 + w;  // 6250 blocks x 8 warps = 50000 exactly
    const float* row = x + (size_t)n * 544;

    float fv = row[512 + lane];
    float mu = warp_sum(fv) * (1.f / 32.f);
    float qq = warp_sum(fv * fv) * (1.f / 32.f);
    float fr = rsqrtf(qq - mu * mu + EPS);
    float fn = (fv - mu) * fr * ln_g[lane] + ln_b[lane];

    float acc[16];
    #pragma unroll
    for (int o = 0; o < 16; o++) acc[o] = 0.f;
    #pragma unroll
    for (int i = 0; i < 16; i++) {
        int c = lane + 32 * i;
        float xv = row[c];
        #pragma unroll
        for (int o = 0; o < 16; o++) acc[o] += xv * g_Wc2[o * 512 + c];
    }
    float xc = 0.f;
    #pragma unroll
    for (int o = 0; o < 16; o++) {
        float v = warp_sum(acc[o]);
        if (lane == o) xc = v + g_bc2[o];
    }

    float* zr = g_z + (size_t)n * 48;
    if (lane < 16) zr[lane] = xc;
    zr[16 + lane] = fn;

    if (lane < 16) { atomicAdd(&sh_s[lane], xc); atomicAdd(&sh_q[lane], xc * xc); }
    atomicAdd(&sh_s[16 + lane], fn);
    atomicAdd(&sh_q[16 + lane], fn * fn);
    __syncthreads();
    if (tid < 48) { atomicAdd(&g_sum2[tid], sh_s[tid]); atomicAdd(&g_sumsq2[tid], sh_q[tid]); }
}

// --------------- per node: t = relu(Wp2 z + bp2), plus attention logits -----
__global__ void k_node_t() {
    __shared__ float wp[64 * 49];
    __shared__ float zb[8][48];
    int tid = threadIdx.x;
    for (int i = tid; i < 64 * 48; i += 256) {
        int o = i / 48, k = i - o * 48;
        wp[o * 49 + k] = g_Wp2[i];
    }
    __syncthreads();
    int w = tid >> 5, lane = tid & 31;
    int n = blockIdx.x * 8 + w;
    const float* zr = g_z + (size_t)n * 48;
    zb[w][lane] = zr[lane];
    if (lane < 16) zb[w][32 + lane] = zr[32 + lane];
    __syncwarp();
    float t0 = g_bp2[lane], t1 = g_bp2[lane + 32];
    #pragma unroll
    for (int k = 0; k < 48; k++) {
        float zv = zb[w][k];
        t0 += wp[lane * 49 + k] * zv;
        t1 += wp[(lane + 32) * 49 + k] * zv;
    }
    t0 = fmaxf(t0, 0.f);
    t1 = fmaxf(t1, 0.f);
    g_t[(size_t)n * 64 + lane]      = t0;
    g_t[(size_t)n * 64 + lane + 32] = t1;

    // attention logits: a_src[n,hd] = t . wsrc[hd], a_dst likewise
    #pragma unroll
    for (int hd = 0; hd < 4; hd++) {
        float ps = t0 * g_wsrc[hd * 64 + lane] + t1 * g_wsrc[hd * 64 + 32 + lane];
        float pd = t0 * g_wdst[hd * 64 + lane] + t1 * g_wdst[hd * 64 + 32 + lane];
        float vs = warp_sum(ps);
        float vd = warp_sum(pd);
        if (lane == 0) { g_asrc[n * 4 + hd] = vs; g_adst[n * 4 + hd] = vd; }
    }
}

// ------------------------- CSR build ----------------------------------------
__global__ void k_deg(const int* __restrict__ ei) {
    int e = blockIdx.x * 256 + threadIdx.x;
    atomicAdd(&g_deg[ei[Ee + e]], 1);
}

__global__ void k_scan() {  // single block, 1024 threads
    __shared__ int sh[1024];
    const int per = (Nn + 1023) / 1024;  // 49
    int t = threadIdx.x;
    int base = t * per;
    int sum = 0;
    for (int i = 0; i < per; i++) {
        int idx = base + i;
        if (idx < Nn) sum += g_deg[idx];
    }
    sh[t] = sum;
    __syncthreads();
    for (int off = 1; off < 1024; off <<= 1) {
        int v = (t >= off) ? sh[t - off] : 0;
        __syncthreads();
        sh[t] += v;
        __syncthreads();
    }
    int offset = (t == 0) ? 0 : sh[t - 1];
    for (int i = 0; i < per; i++) {
        int idx = base + i;
        if (idx < Nn) {
            int d = g_deg[idx];
            g_rowptr[idx] = offset;
            g_cursor[idx] = offset;
            offset += d;
        }
    }
    if (t == 0) g_rowptr[Nn] = Ee;
}

__global__ void k_scatter(const int* __restrict__ ei) {
    int e = blockIdx.x * 256 + threadIdx.x;
    int di = ei[Ee + e];
    int pos = atomicAdd(&g_cursor[di], 1);
    g_col[pos] = ei[e];
}

// --------- fused softmax + aggregation in t-space: warp per dst node --------
// out[n, hd*64+k] = (sum_e ex_e,hd * t[src_e, k]) / (sum_e ex_e,hd)
__global__ void k_agg() {
    int tid = threadIdx.x;
    int w = tid >> 5, lane = tid & 31;
    int n = blockIdx.x * 8 + w;
    int r0 = g_rowptr[n], r1 = g_rowptr[n + 1];
    float4 ad = *(const float4*)&g_adst[n * 4];

    float acc[8];
    #pragma unroll
    for (int i = 0; i < 8; i++) acc[i] = 0.f;
    float s0 = 0.f, s1 = 0.f, s2 = 0.f, s3 = 0.f;

    for (int base = r0; base < r1; base += 32) {
        int cnt = min(32, r1 - base);
        int si = 0;
        float ex0 = 0.f, ex1 = 0.f, ex2 = 0.f, ex3 = 0.f;
        if (lane < cnt) {
            si = g_col[base + lane];
            float4 as = *(const float4*)&g_asrc[si * 4];
            float e0 = as.x + ad.x, e1 = as.y + ad.y, e2 = as.z + ad.z, e3 = as.w + ad.w;
            e0 = e0 > 0.f ? e0 : 0.2f * e0;
            e1 = e1 > 0.f ? e1 : 0.2f * e1;
            e2 = e2 > 0.f ? e2 : 0.2f * e2;
            e3 = e3 > 0.f ? e3 : 0.2f * e3;
            ex0 = expf(e0); ex1 = expf(e1); ex2 = expf(e2); ex3 = expf(e3);
            s0 += ex0; s1 += ex1; s2 += ex2; s3 += ex3;
        }
        for (int j = 0; j < cnt; j++) {
            int sj   = __shfl_sync(0xffffffffu, si, j);
            float a0 = __shfl_sync(0xffffffffu, ex0, j);
            float a1 = __shfl_sync(0xffffffffu, ex1, j);
            float a2 = __shfl_sync(0xffffffffu, ex2, j);
            float a3 = __shfl_sync(0xffffffffu, ex3, j);
            const float* tr = g_t + (size_t)sj * 64;
            float u0 = tr[lane], u1 = tr[lane + 32];
            acc[0] += a0 * u0; acc[1] += a0 * u1;
            acc[2] += a1 * u0; acc[3] += a1 * u1;
            acc[4] += a2 * u0; acc[5] += a2 * u1;
            acc[6] += a3 * u0; acc[7] += a3 * u1;
        }
    }
    s0 = warp_sum(s0); s1 = warp_sum(s1); s2 = warp_sum(s2); s3 = warp_sum(s3);
    float i0 = 1.f / fmaxf(s0, 1e-16f);
    float i1 = 1.f / fmaxf(s1, 1e-16f);
    float i2 = 1.f / fmaxf(s2, 1e-16f);
    float i3 = 1.f / fmaxf(s3, 1e-16f);
    float* o = g_aggt + (size_t)n * 256;
    o[lane]            = acc[0] * i0;  o[lane + 32]       = acc[1] * i0;
    o[64 + lane]       = acc[2] * i1;  o[64 + 32 + lane]  = acc[3] * i1;
    o[128 + lane]      = acc[4] * i2;  o[128 + 32 + lane] = acc[5] * i2;
    o[192 + lane]      = acc[6] * i3;  o[192 + 32 + lane] = acc[7] * i3;
}

// -------- GEMM: out[:, hd block] = aggt[:, hd block] @ Wg[hd block]^T + bn3 stats
__global__ void k_gemm_out(const float* __restrict__ Wg) {
    __shared__ float tsh[64 * 68];
    __shared__ float wsh[64 * 68];
    int n0 = blockIdx.x * 64;
    int hd = blockIdx.y;
    int out0 = hd * 64;
    int tid = threadIdx.x;

    for (int i = tid; i < 64 * 16; i += 256) {
        int r = i >> 4, c = (i & 15) << 2;
        float4 v = make_float4(0.f, 0.f, 0.f, 0.f);
        int n = n0 + r;
        if (n < Nn) v = *(const float4*)&g_aggt[(size_t)n * 256 + out0 + c];
        *(float4*)&tsh[r * 68 + c] = v;
        float4 wv = *(const float4*)&Wg[(size_t)(out0 + r) * 64 + c];
        *(float4*)&wsh[r * 68 + c] = wv;
    }
    __syncthreads();

    int tx = tid & 31, ty = tid >> 5;
    float acc[8][2];
    #pragma unroll
    for (int i = 0; i < 8; i++) { acc[i][0] = 0.f; acc[i][1] = 0.f; }

    #pragma unroll 4
    for (int k = 0; k < 64; k += 4) {
        float4 tv[8], wv[2];
        #pragma unroll
        for (int i = 0; i < 8; i++) tv[i] = *(float4*)&tsh[(ty * 8 + i) * 68 + k];
        wv[0] = *(float4*)&wsh[tx * 68 + k];
        wv[1] = *(float4*)&wsh[(tx + 32) * 68 + k];
        #pragma unroll
        for (int i = 0; i < 8; i++) {
            #pragma unroll
            for (int o = 0; o < 2; o++) {
                acc[i][o] += tv[i].x * wv[o].x;
                acc[i][o] += tv[i].y * wv[o].y;
                acc[i][o] += tv[i].z * wv[o].z;
                acc[i][o] += tv[i].w * wv[o].w;
            }
        }
    }
    float ps0 = 0.f, pq0 = 0.f, ps1 = 0.f, pq1 = 0.f;
    #pragma unroll
    for (int i = 0; i < 8; i++) {
        int n = n0 + ty * 8 + i;
        if (n < Nn) {
            g_out[(size_t)n * 256 + out0 + tx]      = acc[i][0];
            g_out[(size_t)n * 256 + out0 + tx + 32] = acc[i][1];
            ps0 += acc[i][0]; pq0 += acc[i][0] * acc[i][0];
            ps1 += acc[i][1]; pq1 += acc[i][1] * acc[i][1];
        }
    }
    atomicAdd(&g_sum3[out0 + tx], ps0);
    atomicAdd(&g_sumsq3[out0 + tx], pq0);
    atomicAdd(&g_sum3[out0 + tx + 32], ps1);
    atomicAdd(&g_sumsq3[out0 + tx + 32], pq1);
}

// ------------------------- bn3 + elu + graph pooling -------------------------
__global__ void k_pool(const int* __restrict__ batch) {
    int n = blockIdx.x, c = threadIdx.x;
    int b = batch[n];
    float v = g_out[(size_t)n * 256 + c] * g_scale3[c] + g_shift3[c];
    v = v > 0.f ? v : (expf(v) - 1.f);
    atomicAdd(&g_pooled[b * 256 + c], v);
    if (c == 0) atomicAdd(&g_cnt[b], 1.f);
}

// ------------------------- head MLP ------------------------------------------
__global__ void k_head(const float* __restrict__ W1, const float* __restrict__ b1,
                       const float* __restrict__ W2, const float* __restrict__ b2,
                       float* __restrict__ out) {
    __shared__ float p[256];
    __shared__ float hm[64];
    int g = blockIdx.x, t = threadIdx.x;
    float cnt = fmaxf(g_cnt[g], 1.f);
    p[t] = g_pooled[g * 256 + t] / cnt;
    __syncthreads();
    if (t < 64) {
        float a = b1[t];
        #pragma unroll 8
        for (int c = 0; c < 256; c++) a += p[c] * W1[t * 256 + c];
        hm[t] = fmaxf(a, 0.f);
    }
    __syncthreads();
    if (t < 2) {
        float a = b2[t];
        #pragma unroll
        for (int k = 0; k < 64; k++) a += hm[k] * W2[t * 64 + k];
        out[g * 2 + t] = a;
    }
}

// ------------------------- launch ---------------------------------------------
extern "C" void kernel_launch(void* const* d_in, const int* in_sizes, int n_in,
                              void* d_out, int out_size) {
    const float* x       = (const float*)d_in[0];
    const int*   ei      = (const int*)d_in[1];
    const int*   batch   = (const int*)d_in[2];
    const float* ln_g    = (const float*)d_in[3];
    const float* ln_b    = (const float*)d_in[4];
    const float* bn1_g   = (const float*)d_in[5];
    const float* bn1_b   = (const float*)d_in[6];
    const float* Wc      = (const float*)d_in[7];
    const float* bc      = (const float*)d_in[8];
    const float* bn2_g   = (const float*)d_in[9];
    const float* bn2_b   = (const float*)d_in[10];
    const float* Wp      = (const float*)d_in[11];
    const float* bp      = (const float*)d_in[12];
    const float* Wg      = (const float*)d_in[13];
    const float* att_src = (const float*)d_in[14];
    const float* att_dst = (const float*)d_in[15];
    // d_in[16] = bg : cancels under bn3 (pure mean shift) -> unused
    const float* bn3_g   = (const float*)d_in[17];
    const float* bn3_b   = (const float*)d_in[18];
    const float* W1      = (const float*)d_in[19];
    const float* b1      = (const float*)d_in[20];
    const float* W2      = (const float*)d_in[21];
    const float* b2      = (const float*)d_in[22];
    float* out = (float*)d_out;

    k_init<<<576, 256>>>();
    k_bn1_stats<<<1000, 512>>>(x);
    k_deg<<<3125, 256>>>(ei);
    k_fin<<<2, 256>>>(bn1_g, bn1_b, 0, 512, 1.f / Nn);
    k_fold_wc<<<16, 512>>>(Wc, bc);
    k_scan<<<1, 1024>>>();
    k_scatter<<<3125, 256>>>(ei);
    k_node_z<<<6250, 256>>>(x, ln_g, ln_b);
    k_fin<<<1, 256>>>(bn2_g, bn2_b, 1, 48, 1.f / Nn);
    k_fold_wp<<<64, 64>>>(Wp, bp);
    k_fold_att<<<4, 64>>>(Wg, att_src, att_dst);
    k_node_t<<<6250, 256>>>();
    k_agg<<<6250, 256>>>();
    dim3 gh(782, 4);
    k_gemm_out<<<gh, 256>>>(Wg);
    k_fin<<<1, 256>>>(bn3_g, bn3_b, 2, 256, 1.f / Nn);
    k_pool<<<Nn, 256>>>(batch);
    k_head<<<Gg, 256>>>(W1, b1, W2, b2, out);
}

// round 4
// speedup vs baseline: 1.3216x; 1.1306x over previous
#include <cuda_runtime.h>
#include <math.h>
#include <stdint.h>

#define Nn 50000
#define Ee 800000
#define Gg 512
#define EPS 1e-5f

// ------------------------- device scratch (static, no allocs) ---------------
__device__ float g_sum1[512], g_sumsq1[512];
__device__ __align__(16) float g_Wc2[16 * 512];
__device__ float g_bc2[16];
__device__ __align__(16) float g_z[(size_t)Nn * 48];
__device__ float g_sum2[48], g_sumsq2[48];
__device__ float g_Wp2[64 * 48], g_bp2[64];
__device__ __align__(16) float g_t[(size_t)Nn * 64];
__device__ float g_wsrc[4 * 64], g_wdst[4 * 64];
__device__ __align__(16) float g_asrc[Nn * 4];
__device__ __align__(16) float g_adst[Nn * 4];
__device__ int g_deg[Nn];
__device__ int g_rowptr[Nn + 1];
__device__ int g_cursor[Nn];
__device__ int g_col[Ee];
__device__ __align__(16) float g_aggt[(size_t)Nn * 256];   // per-head aggregated t
__device__ __align__(16) float g_out[(size_t)Nn * 256];    // aggt @ Wg^T (pre-bn3)
__device__ float g_sum3[256], g_sumsq3[256];
__device__ float g_pooled[Gg * 256];
__device__ float g_cnt[Gg];

// ------------------------- helpers ------------------------------------------
__device__ __forceinline__ float warp_sum(float v) {
    #pragma unroll
    for (int off = 16; off; off >>= 1) v += __shfl_xor_sync(0xffffffffu, v, off);
    return v;
}

// ------------------------- init (per-launch reset; graph-replay safe) -------
__global__ void k_init() {
    int i = blockIdx.x * blockDim.x + threadIdx.x;
    int stride = gridDim.x * blockDim.x;
    for (int j = i; j < Nn; j += stride) g_deg[j] = 0;
    for (int j = i; j < Gg * 256; j += stride) g_pooled[j] = 0.f;
    if (i < 512) { g_sum1[i] = 0.f; g_sumsq1[i] = 0.f; }
    if (i < 256) { g_sum3[i] = 0.f; g_sumsq3[i] = 0.f; }
    if (i < 48)  { g_sum2[i] = 0.f; g_sumsq2[i] = 0.f; }
    if (i < Gg)  g_cnt[i] = 0.f;
}

// ---------- merged: bn1 stats (blocks 0..999) + degree count (blocks 1000+) -
__global__ void k_pre(const float* __restrict__ x, const int* __restrict__ ei) {
    int b = blockIdx.x;
    if (b < 1000) {
        int c = threadIdx.x;  // 512 threads
        float s = 0.f, q = 0.f;
        for (int r = b; r < Nn; r += 1000) {
            float v = x[(size_t)r * 544 + c];
            s += v; q += v * v;
        }
        atomicAdd(&g_sum1[c], s);
        atomicAdd(&g_sumsq1[c], q);
    } else {
        int e = (b - 1000) * 512 + threadIdx.x;
        if (e < Ee) atomicAdd(&g_deg[ei[Ee + e]], 1);
    }
}

// fold bn1 into Wc (bn1 finalize inline)
__global__ void k_fold_wc(const float* __restrict__ Wc, const float* __restrict__ bc,
                          const float* __restrict__ bn1_g, const float* __restrict__ bn1_b) {
    __shared__ float red[512];
    int o = blockIdx.x, t = threadIdx.x;
    const float invN = 1.f / Nn;
    float mean = g_sum1[t] * invN;
    float var  = g_sumsq1[t] * invN - mean * mean;
    float r = rsqrtf(var + EPS);
    float sc = r * bn1_g[t];
    float sh = bn1_b[t] - mean * sc;
    float w = Wc[o * 512 + t];
    g_Wc2[o * 512 + t] = w * sc;
    red[t] = w * sh;
    __syncthreads();
    for (int s = 256; s; s >>= 1) { if (t < s) red[t] += red[t + s]; __syncthreads(); }
    if (t == 0) g_bc2[o] = bc[o] + red[0];
}

// ------------------------- CSR build ----------------------------------------
__global__ void k_scan() {  // single block, 1024 threads
    __shared__ int sh[1024];
    const int per = (Nn + 1023) / 1024;  // 49
    int t = threadIdx.x;
    int base = t * per;
    int sum = 0;
    for (int i = 0; i < per; i++) {
        int idx = base + i;
        if (idx < Nn) sum += g_deg[idx];
    }
    sh[t] = sum;
    __syncthreads();
    for (int off = 1; off < 1024; off <<= 1) {
        int v = (t >= off) ? sh[t - off] : 0;
        __syncthreads();
        sh[t] += v;
        __syncthreads();
    }
    int offset = (t == 0) ? 0 : sh[t - 1];
    for (int i = 0; i < per; i++) {
        int idx = base + i;
        if (idx < Nn) {
            int d = g_deg[idx];
            g_rowptr[idx] = offset;
            g_cursor[idx] = offset;
            offset += d;
        }
    }
    if (t == 0) g_rowptr[Nn] = Ee;
}

__global__ void k_scatter(const int* __restrict__ ei) {
    int e = blockIdx.x * 256 + threadIdx.x;
    int di = ei[Ee + e];
    int pos = atomicAdd(&g_cursor[di], 1);
    g_col[pos] = ei[e];
}

// ------------------------- per node: LN(f) + Wc2 matmul -> z, bn2 stats -----
__global__ void k_node_z(const float* __restrict__ x,
                         const float* __restrict__ ln_g, const float* __restrict__ ln_b) {
    __shared__ float sh_s[48], sh_q[48];
    int tid = threadIdx.x;
    if (tid < 48) { sh_s[tid] = 0.f; sh_q[tid] = 0.f; }
    __syncthreads();
    int w = tid >> 5, lane = tid & 31;
    int n = blockIdx.x * 8 + w;  // 6250 blocks x 8 warps = 50000 exactly
    const float* row = x + (size_t)n * 544;

    // layernorm on f = x[:, 512:544]
    float fv = row[512 + lane];
    float mu = warp_sum(fv) * (1.f / 32.f);
    float qq = warp_sum(fv * fv) * (1.f / 32.f);
    float fr = rsqrtf(qq - mu * mu + EPS);
    float fn = (fv - mu) * fr * ln_g[lane] + ln_b[lane];

    // x_cnn: vectorized. lane covers columns {4*lane + 128*i}, i=0..3
    float4 xv[4];
    #pragma unroll
    for (int i = 0; i < 4; i++)
        xv[i] = *(const float4*)&row[4 * lane + 128 * i];

    float xc = 0.f;
    #pragma unroll
    for (int o = 0; o < 16; o++) {
        float a = 0.f;
        #pragma unroll
        for (int i = 0; i < 4; i++) {
            float4 wv = *(const float4*)&g_Wc2[o * 512 + 4 * lane + 128 * i];
            a += xv[i].x * wv.x + xv[i].y * wv.y + xv[i].z * wv.z + xv[i].w * wv.w;
        }
        float v = warp_sum(a);
        if (lane == o) xc = v + g_bc2[o];
    }

    float* zr = g_z + (size_t)n * 48;
    if (lane < 16) zr[lane] = xc;
    zr[16 + lane] = fn;

    if (lane < 16) { atomicAdd(&sh_s[lane], xc); atomicAdd(&sh_q[lane], xc * xc); }
    atomicAdd(&sh_s[16 + lane], fn);
    atomicAdd(&sh_q[16 + lane], fn * fn);
    __syncthreads();
    if (tid < 48) { atomicAdd(&g_sum2[tid], sh_s[tid]); atomicAdd(&g_sumsq2[tid], sh_q[tid]); }
}

// merged: fold bn2 into Wp (blocks 0..63) + fold att through Wg (blocks 64..67)
__global__ void k_fold2(const float* __restrict__ Wp, const float* __restrict__ bp,
                        const float* __restrict__ bn2_g, const float* __restrict__ bn2_b,
                        const float* __restrict__ Wg,
                        const float* __restrict__ att_src, const float* __restrict__ att_dst) {
    int b = blockIdx.x, t = threadIdx.x;  // 64 threads
    if (b < 64) {
        __shared__ float red[64];
        float p = 0.f;
        if (t < 48) {
            const float invN = 1.f / Nn;
            float mean = g_sum2[t] * invN;
            float var  = g_sumsq2[t] * invN - mean * mean;
            float r = rsqrtf(var + EPS);
            float sc = r * bn2_g[t];
            float sh = bn2_b[t] - mean * sc;
            float w = Wp[b * 48 + t];
            g_Wp2[b * 48 + t] = w * sc;
            p = w * sh;
        }
        red[t] = p;
        __syncthreads();
        for (int s = 32; s; s >>= 1) { if (t < s) red[t] += red[t + s]; __syncthreads(); }
        if (t == 0) g_bp2[b] = bp[b] + red[0];
    } else {
        int hd = b - 64;
        __shared__ float as[64], ad[64];
        as[t] = att_src[hd * 64 + t];
        ad[t] = att_dst[hd * 64 + t];
        __syncthreads();
        float s = 0.f, d = 0.f;
        #pragma unroll 8
        for (int j = 0; j < 64; j++) {
            float w = Wg[(size_t)(hd * 64 + j) * 64 + t];
            s += as[j] * w;
            d += ad[j] * w;
        }
        g_wsrc[hd * 64 + t] = s;
        g_wdst[hd * 64 + t] = d;
    }
}

// --------------- per node: t = relu(Wp2 z + bp2), plus attention logits -----
__global__ void k_node_t() {
    __shared__ float wp[64 * 49];
    __shared__ float zb[8][48];
    int tid = threadIdx.x;
    for (int i = tid; i < 64 * 48; i += 256) {
        int o = i / 48, k = i - o * 48;
        wp[o * 49 + k] = g_Wp2[i];
    }
    __syncthreads();
    int w = tid >> 5, lane = tid & 31;
    int n = blockIdx.x * 8 + w;
    const float* zr = g_z + (size_t)n * 48;
    zb[w][lane] = zr[lane];
    if (lane < 16) zb[w][32 + lane] = zr[32 + lane];
    __syncwarp();
    float t0 = g_bp2[lane], t1 = g_bp2[lane + 32];
    #pragma unroll
    for (int k = 0; k < 48; k++) {
        float zv = zb[w][k];
        t0 += wp[lane * 49 + k] * zv;
        t1 += wp[(lane + 32) * 49 + k] * zv;
    }
    t0 = fmaxf(t0, 0.f);
    t1 = fmaxf(t1, 0.f);
    g_t[(size_t)n * 64 + lane]      = t0;
    g_t[(size_t)n * 64 + lane + 32] = t1;

    #pragma unroll
    for (int hd = 0; hd < 4; hd++) {
        float ps = t0 * g_wsrc[hd * 64 + lane] + t1 * g_wsrc[hd * 64 + 32 + lane];
        float pd = t0 * g_wdst[hd * 64 + lane] + t1 * g_wdst[hd * 64 + 32 + lane];
        float vs = warp_sum(ps);
        float vd = warp_sum(pd);
        if (lane == 0) { g_asrc[n * 4 + hd] = vs; g_adst[n * 4 + hd] = vd; }
    }
}

// --------- fused softmax + aggregation in t-space: warp per dst node --------
__global__ void k_agg() {
    int tid = threadIdx.x;
    int w = tid >> 5, lane = tid & 31;
    int n = blockIdx.x * 8 + w;
    int r0 = g_rowptr[n], r1 = g_rowptr[n + 1];
    float4 ad = *(const float4*)&g_adst[n * 4];

    float acc[8];
    #pragma unroll
    for (int i = 0; i < 8; i++) acc[i] = 0.f;
    float s0 = 0.f, s1 = 0.f, s2 = 0.f, s3 = 0.f;

    for (int base = r0; base < r1; base += 32) {
        int cnt = min(32, r1 - base);
        int si = 0;
        float ex0 = 0.f, ex1 = 0.f, ex2 = 0.f, ex3 = 0.f;
        if (lane < cnt) {
            si = g_col[base + lane];
            float4 as = *(const float4*)&g_asrc[si * 4];
            float e0 = as.x + ad.x, e1 = as.y + ad.y, e2 = as.z + ad.z, e3 = as.w + ad.w;
            e0 = e0 > 0.f ? e0 : 0.2f * e0;
            e1 = e1 > 0.f ? e1 : 0.2f * e1;
            e2 = e2 > 0.f ? e2 : 0.2f * e2;
            e3 = e3 > 0.f ? e3 : 0.2f * e3;
            ex0 = expf(e0); ex1 = expf(e1); ex2 = expf(e2); ex3 = expf(e3);
            s0 += ex0; s1 += ex1; s2 += ex2; s3 += ex3;
        }
        for (int j = 0; j < cnt; j++) {
            int sj   = __shfl_sync(0xffffffffu, si, j);
            float a0 = __shfl_sync(0xffffffffu, ex0, j);
            float a1 = __shfl_sync(0xffffffffu, ex1, j);
            float a2 = __shfl_sync(0xffffffffu, ex2, j);
            float a3 = __shfl_sync(0xffffffffu, ex3, j);
            const float* tr = g_t + (size_t)sj * 64;
            float u0 = tr[lane], u1 = tr[lane + 32];
            acc[0] += a0 * u0; acc[1] += a0 * u1;
            acc[2] += a1 * u0; acc[3] += a1 * u1;
            acc[4] += a2 * u0; acc[5] += a2 * u1;
            acc[6] += a3 * u0; acc[7] += a3 * u1;
        }
    }
    s0 = warp_sum(s0); s1 = warp_sum(s1); s2 = warp_sum(s2); s3 = warp_sum(s3);
    float i0 = 1.f / fmaxf(s0, 1e-16f);
    float i1 = 1.f / fmaxf(s1, 1e-16f);
    float i2 = 1.f / fmaxf(s2, 1e-16f);
    float i3 = 1.f / fmaxf(s3, 1e-16f);
    float* o = g_aggt + (size_t)n * 256;
    o[lane]            = acc[0] * i0;  o[lane + 32]       = acc[1] * i0;
    o[64 + lane]       = acc[2] * i1;  o[64 + 32 + lane]  = acc[3] * i1;
    o[128 + lane]      = acc[4] * i2;  o[128 + 32 + lane] = acc[5] * i2;
    o[192 + lane]      = acc[6] * i3;  o[192 + 32 + lane] = acc[7] * i3;
}

// -------- GEMM: out[:, hd] = aggt[:, hd] @ Wg[hd]^T, plus bn3 stats ----------
__global__ void k_gemm_out(const float* __restrict__ Wg) {
    __shared__ float tsh[64 * 68];
    __shared__ float wsh[64 * 68];
    int n0 = blockIdx.x * 64;
    int hd = blockIdx.y;
    int out0 = hd * 64;
    int tid = threadIdx.x;

    for (int i = tid; i < 64 * 16; i += 256) {
        int r = i >> 4, c = (i & 15) << 2;
        float4 v = make_float4(0.f, 0.f, 0.f, 0.f);
        int n = n0 + r;
        if (n < Nn) v = *(const float4*)&g_aggt[(size_t)n * 256 + out0 + c];
        *(float4*)&tsh[r * 68 + c] = v;
        float4 wv = *(const float4*)&Wg[(size_t)(out0 + r) * 64 + c];
        *(float4*)&wsh[r * 68 + c] = wv;
    }
    __syncthreads();

    int tx = tid & 31, ty = tid >> 5;
    float acc[8][2];
    #pragma unroll
    for (int i = 0; i < 8; i++) { acc[i][0] = 0.f; acc[i][1] = 0.f; }

    #pragma unroll 4
    for (int k = 0; k < 64; k += 4) {
        float4 tv[8], wv[2];
        #pragma unroll
        for (int i = 0; i < 8; i++) tv[i] = *(float4*)&tsh[(ty * 8 + i) * 68 + k];
        wv[0] = *(float4*)&wsh[tx * 68 + k];
        wv[1] = *(float4*)&wsh[(tx + 32) * 68 + k];
        #pragma unroll
        for (int i = 0; i < 8; i++) {
            #pragma unroll
            for (int o = 0; o < 2; o++) {
                acc[i][o] += tv[i].x * wv[o].x;
                acc[i][o] += tv[i].y * wv[o].y;
                acc[i][o] += tv[i].z * wv[o].z;
                acc[i][o] += tv[i].w * wv[o].w;
            }
        }
    }
    float ps0 = 0.f, pq0 = 0.f, ps1 = 0.f, pq1 = 0.f;
    #pragma unroll
    for (int i = 0; i < 8; i++) {
        int n = n0 + ty * 8 + i;
        if (n < Nn) {
            g_out[(size_t)n * 256 + out0 + tx]      = acc[i][0];
            g_out[(size_t)n * 256 + out0 + tx + 32] = acc[i][1];
            ps0 += acc[i][0]; pq0 += acc[i][0] * acc[i][0];
            ps1 += acc[i][1]; pq1 += acc[i][1] * acc[i][1];
        }
    }
    atomicAdd(&g_sum3[out0 + tx], ps0);
    atomicAdd(&g_sumsq3[out0 + tx], pq0);
    atomicAdd(&g_sum3[out0 + tx + 32], ps1);
    atomicAdd(&g_sumsq3[out0 + tx + 32], pq1);
}

// --------------- bn3 (inline finalize) + elu + graph pooling -----------------
__global__ void k_pool(const int* __restrict__ batch,
                       const float* __restrict__ bn3_g, const float* __restrict__ bn3_b) {
    int n = blockIdx.x, c = threadIdx.x;
    const float invN = 1.f / Nn;
    float mean = g_sum3[c] * invN;
    float var  = g_sumsq3[c] * invN - mean * mean;
    float r = rsqrtf(var + EPS);
    float sc = r * bn3_g[c];
    float sh = bn3_b[c] - mean * sc;
    int b = batch[n];
    float v = g_out[(size_t)n * 256 + c] * sc + sh;
    v = v > 0.f ? v : (expf(v) - 1.f);
    atomicAdd(&g_pooled[b * 256 + c], v);
    if (c == 0) atomicAdd(&g_cnt[b], 1.f);
}

// ------------------------- head MLP ------------------------------------------
__global__ void k_head(const float* __restrict__ W1, const float* __restrict__ b1,
                       const float* __restrict__ W2, const float* __restrict__ b2,
                       float* __restrict__ out) {
    __shared__ float p[256];
    __shared__ float hm[64];
    int g = blockIdx.x, t = threadIdx.x;
    float cnt = fmaxf(g_cnt[g], 1.f);
    p[t] = g_pooled[g * 256 + t] / cnt;
    __syncthreads();
    if (t < 64) {
        float a = b1[t];
        #pragma unroll 8
        for (int c = 0; c < 256; c++) a += p[c] * W1[t * 256 + c];
        hm[t] = fmaxf(a, 0.f);
    }
    __syncthreads();
    if (t < 2) {
        float a = b2[t];
        #pragma unroll
        for (int k = 0; k < 64; k++) a += hm[k] * W2[t * 64 + k];
        out[g * 2 + t] = a;
    }
}

// ------------------------- launch ---------------------------------------------
extern "C" void kernel_launch(void* const* d_in, const int* in_sizes, int n_in,
                              void* d_out, int out_size) {
    const float* x       = (const float*)d_in[0];
    const int*   ei      = (const int*)d_in[1];
    const int*   batch   = (const int*)d_in[2];
    const float* ln_g    = (const float*)d_in[3];
    const float* ln_b    = (const float*)d_in[4];
    const float* bn1_g   = (const float*)d_in[5];
    const float* bn1_b   = (const float*)d_in[6];
    const float* Wc      = (const float*)d_in[7];
    const float* bc      = (const float*)d_in[8];
    const float* bn2_g   = (const float*)d_in[9];
    const float* bn2_b   = (const float*)d_in[10];
    const float* Wp      = (const float*)d_in[11];
    const float* bp      = (const float*)d_in[12];
    const float* Wg      = (const float*)d_in[13];
    const float* att_src = (const float*)d_in[14];
    const float* att_dst = (const float*)d_in[15];
    // d_in[16] = bg : cancels under bn3 (pure mean shift) -> unused
    const float* bn3_g   = (const float*)d_in[17];
    const float* bn3_b   = (const float*)d_in[18];
    const float* W1      = (const float*)d_in[19];
    const float* b1      = (const float*)d_in[20];
    const float* W2      = (const float*)d_in[21];
    const float* b2      = (const float*)d_in[22];
    float* out = (float*)d_out;

    k_init<<<576, 256>>>();
    k_pre<<<1000 + (Ee + 511) / 512, 512>>>(x, ei);
    k_fold_wc<<<16, 512>>>(Wc, bc, bn1_g, bn1_b);
    k_scan<<<1, 1024>>>();
    k_scatter<<<3125, 256>>>(ei);
    k_node_z<<<6250, 256>>>(x, ln_g, ln_b);
    k_fold2<<<68, 64>>>(Wp, bp, bn2_g, bn2_b, Wg, att_src, att_dst);
    k_node_t<<<6250, 256>>>();
    k_agg<<<6250, 256>>>();
    dim3 gh(782, 4);
    k_gemm_out<<<gh, 256>>>(Wg);
    k_pool<<<Nn, 256>>>(batch, bn3_g, bn3_b);
    k_head<<<Gg, 256>>>(W1, b1, W2, b2, out);
}

// round 5
// speedup vs baseline: 1.5581x; 1.1790x over previous
#include <cuda_runtime.h>
#include <math.h>
#include <stdint.h>

#define Nn 50000
#define Ee 800000
#define Gg 512
#define EPS 1e-5f
#define NCHUNK ((Nn + 255) / 256)   // 196

// ------------------------- device scratch (static, no allocs) ---------------
__device__ float g_sum1[512], g_sumsq1[512];
__device__ __align__(16) float g_Wc2[16 * 512];
__device__ float g_bc2[16];
__device__ __align__(16) float g_z[(size_t)Nn * 48];
__device__ float g_sum2[48], g_sumsq2[48];
__device__ float g_Wp2[64 * 48], g_bp2[64];
__device__ __align__(16) float g_t[(size_t)Nn * 64];
__device__ float g_wsrc[4 * 64], g_wdst[4 * 64];
__device__ __align__(16) float g_asrc[Nn * 4];
__device__ __align__(16) float g_adst[Nn * 4];
__device__ int g_deg[Nn];
__device__ int g_rowptr[Nn + 1];
__device__ int g_cursor[Nn];
__device__ int g_chunksum[NCHUNK];
__device__ int g_chunkoff[NCHUNK];
__device__ int g_col[Ee];
__device__ __align__(16) float g_aggt[(size_t)Nn * 256];   // per-head aggregated t
__device__ __align__(16) float g_out[(size_t)Nn * 256];    // aggt @ Wg^T (pre-bn3)
__device__ float g_sum3[256], g_sumsq3[256];
__device__ float g_pooled[Gg * 256];
__device__ float g_cnt[Gg];

// ------------------------- helpers ------------------------------------------
__device__ __forceinline__ float warp_sum(float v) {
    #pragma unroll
    for (int off = 16; off; off >>= 1) v += __shfl_xor_sync(0xffffffffu, v, off);
    return v;
}
__device__ __forceinline__ int warp_sum_i(int v) {
    #pragma unroll
    for (int off = 16; off; off >>= 1) v += __shfl_xor_sync(0xffffffffu, v, off);
    return v;
}

// ------------------------- init (per-launch reset; graph-replay safe) -------
__global__ void k_init() {
    int i = blockIdx.x * blockDim.x + threadIdx.x;
    int stride = gridDim.x * blockDim.x;
    for (int j = i; j < Nn; j += stride) g_deg[j] = 0;
    for (int j = i; j < Gg * 256; j += stride) g_pooled[j] = 0.f;
    if (i < 512) { g_sum1[i] = 0.f; g_sumsq1[i] = 0.f; }
    if (i < 256) { g_sum3[i] = 0.f; g_sumsq3[i] = 0.f; }
    if (i < 48)  { g_sum2[i] = 0.f; g_sumsq2[i] = 0.f; }
    if (i < Gg)  g_cnt[i] = 0.f;
}

// ---------- merged: bn1 stats (blocks 0..999) + degree count (blocks 1000+) -
__global__ void k_pre(const float* __restrict__ x, const int* __restrict__ ei) {
    int b = blockIdx.x;
    if (b < 1000) {
        int c = threadIdx.x;  // 512 threads
        float s = 0.f, q = 0.f;
        for (int r = b; r < Nn; r += 1000) {
            float v = x[(size_t)r * 544 + c];
            s += v; q += v * v;
        }
        atomicAdd(&g_sum1[c], s);
        atomicAdd(&g_sumsq1[c], q);
    } else {
        int e = (b - 1000) * 512 + threadIdx.x;
        if (e < Ee) atomicAdd(&g_deg[ei[Ee + e]], 1);
    }
}

// fold bn1 into Wc (bn1 finalize inline)
__global__ void k_fold_wc(const float* __restrict__ Wc, const float* __restrict__ bc,
                          const float* __restrict__ bn1_g, const float* __restrict__ bn1_b) {
    __shared__ float red[512];
    int o = blockIdx.x, t = threadIdx.x;
    const float invN = 1.f / Nn;
    float mean = g_sum1[t] * invN;
    float var  = g_sumsq1[t] * invN - mean * mean;
    float r = rsqrtf(var + EPS);
    float sc = r * bn1_g[t];
    float sh = bn1_b[t] - mean * sc;
    float w = Wc[o * 512 + t];
    g_Wc2[o * 512 + t] = w * sc;
    red[t] = w * sh;
    __syncthreads();
    for (int s = 256; s; s >>= 1) { if (t < s) red[t] += red[t + s]; __syncthreads(); }
    if (t == 0) g_bc2[o] = bc[o] + red[0];
}

// ------------------------- CSR build: 3-phase parallel scan ------------------
__global__ void k_scan1() {   // 196 blocks x 256: per-chunk degree sum
    int idx = blockIdx.x * 256 + threadIdx.x;
    int d = (idx < Nn) ? g_deg[idx] : 0;
    int s = warp_sum_i(d);
    __shared__ int sh[8];
    if ((threadIdx.x & 31) == 0) sh[threadIdx.x >> 5] = s;
    __syncthreads();
    if (threadIdx.x < 8) {
        int v = sh[threadIdx.x];
        #pragma unroll
        for (int off = 4; off; off >>= 1) v += __shfl_xor_sync(0xffu, v, off);
        if (threadIdx.x == 0) g_chunksum[blockIdx.x] = v;
    }
}

__global__ void k_scan2() {   // 1 block x 256: exclusive scan of 196 chunk sums
    __shared__ int sh[256];
    int t = threadIdx.x;
    int v = (t < NCHUNK) ? g_chunksum[t] : 0;
    sh[t] = v;
    __syncthreads();
    for (int off = 1; off < 256; off <<= 1) {
        int u = (t >= off) ? sh[t - off] : 0;
        __syncthreads();
        sh[t] += u;
        __syncthreads();
    }
    if (t < NCHUNK) g_chunkoff[t] = sh[t] - v;  // exclusive
}

__global__ void k_scan3() {   // 196 blocks x 256: local exclusive scan + offset
    __shared__ int sh[256];
    int t = threadIdx.x;
    int idx = blockIdx.x * 256 + t;
    int d = (idx < Nn) ? g_deg[idx] : 0;
    sh[t] = d;
    __syncthreads();
    for (int off = 1; off < 256; off <<= 1) {
        int u = (t >= off) ? sh[t - off] : 0;
        __syncthreads();
        sh[t] += u;
        __syncthreads();
    }
    if (idx < Nn) {
        int pos = g_chunkoff[blockIdx.x] + sh[t] - d;  // exclusive prefix
        g_rowptr[idx] = pos;
        g_cursor[idx] = pos;
    }
    if (idx == Nn - 1) g_rowptr[Nn] = Ee;
}

__global__ void k_scatter(const int* __restrict__ ei) {
    int e = blockIdx.x * 256 + threadIdx.x;
    int di = ei[Ee + e];
    int pos = atomicAdd(&g_cursor[di], 1);
    g_col[pos] = ei[e];
}

// ------------------------- per node: LN(f) + Wc2 matmul -> z, bn2 stats -----
__global__ void k_node_z(const float* __restrict__ x,
                         const float* __restrict__ ln_g, const float* __restrict__ ln_b) {
    __shared__ float sh_s[48], sh_q[48];
    int tid = threadIdx.x;
    if (tid < 48) { sh_s[tid] = 0.f; sh_q[tid] = 0.f; }
    __syncthreads();
    int w = tid >> 5, lane = tid & 31;
    int n = blockIdx.x * 8 + w;  // 6250 blocks x 8 warps = 50000 exactly
    const float* row = x + (size_t)n * 544;

    // layernorm on f = x[:, 512:544]
    float fv = row[512 + lane];
    float mu = warp_sum(fv) * (1.f / 32.f);
    float qq = warp_sum(fv * fv) * (1.f / 32.f);
    float fr = rsqrtf(qq - mu * mu + EPS);
    float fn = (fv - mu) * fr * ln_g[lane] + ln_b[lane];

    // x_cnn: vectorized. lane covers columns {4*lane + 128*i}, i=0..3
    float4 xv[4];
    #pragma unroll
    for (int i = 0; i < 4; i++)
        xv[i] = *(const float4*)&row[4 * lane + 128 * i];

    float xc = 0.f;
    #pragma unroll
    for (int o = 0; o < 16; o++) {
        float a = 0.f;
        #pragma unroll
        for (int i = 0; i < 4; i++) {
            float4 wv = *(const float4*)&g_Wc2[o * 512 + 4 * lane + 128 * i];
            a += xv[i].x * wv.x + xv[i].y * wv.y + xv[i].z * wv.z + xv[i].w * wv.w;
        }
        float v = warp_sum(a);
        if (lane == o) xc = v + g_bc2[o];
    }

    float* zr = g_z + (size_t)n * 48;
    if (lane < 16) zr[lane] = xc;
    zr[16 + lane] = fn;

    if (lane < 16) { atomicAdd(&sh_s[lane], xc); atomicAdd(&sh_q[lane], xc * xc); }
    atomicAdd(&sh_s[16 + lane], fn);
    atomicAdd(&sh_q[16 + lane], fn * fn);
    __syncthreads();
    if (tid < 48) { atomicAdd(&g_sum2[tid], sh_s[tid]); atomicAdd(&g_sumsq2[tid], sh_q[tid]); }
}

// merged: fold bn2 into Wp (blocks 0..63) + fold att through Wg (blocks 64..67)
__global__ void k_fold2(const float* __restrict__ Wp, const float* __restrict__ bp,
                        const float* __restrict__ bn2_g, const float* __restrict__ bn2_b,
                        const float* __restrict__ Wg,
                        const float* __restrict__ att_src, const float* __restrict__ att_dst) {
    int b = blockIdx.x, t = threadIdx.x;  // 64 threads
    if (b < 64) {
        __shared__ float red[64];
        float p = 0.f;
        if (t < 48) {
            const float invN = 1.f / Nn;
            float mean = g_sum2[t] * invN;
            float var  = g_sumsq2[t] * invN - mean * mean;
            float r = rsqrtf(var + EPS);
            float sc = r * bn2_g[t];
            float sh = bn2_b[t] - mean * sc;
            float w = Wp[b * 48 + t];
            g_Wp2[b * 48 + t] = w * sc;
            p = w * sh;
        }
        red[t] = p;
        __syncthreads();
        for (int s = 32; s; s >>= 1) { if (t < s) red[t] += red[t + s]; __syncthreads(); }
        if (t == 0) g_bp2[b] = bp[b] + red[0];
    } else {
        int hd = b - 64;
        __shared__ float as[64], ad[64];
        as[t] = att_src[hd * 64 + t];
        ad[t] = att_dst[hd * 64 + t];
        __syncthreads();
        float s = 0.f, d = 0.f;
        #pragma unroll 8
        for (int j = 0; j < 64; j++) {
            float w = Wg[(size_t)(hd * 64 + j) * 64 + t];
            s += as[j] * w;
            d += ad[j] * w;
        }
        g_wsrc[hd * 64 + t] = s;
        g_wdst[hd * 64 + t] = d;
    }
}

// --------------- per node: t = relu(Wp2 z + bp2), plus attention logits -----
__global__ void k_node_t() {
    __shared__ float wp[64 * 49];
    __shared__ float zb[8][48];
    int tid = threadIdx.x;
    for (int i = tid; i < 64 * 48; i += 256) {
        int o = i / 48, k = i - o * 48;
        wp[o * 49 + k] = g_Wp2[i];
    }
    __syncthreads();
    int w = tid >> 5, lane = tid & 31;
    int n = blockIdx.x * 8 + w;
    const float* zr = g_z + (size_t)n * 48;
    zb[w][lane] = zr[lane];
    if (lane < 16) zb[w][32 + lane] = zr[32 + lane];
    __syncwarp();
    float t0 = g_bp2[lane], t1 = g_bp2[lane + 32];
    #pragma unroll
    for (int k = 0; k < 48; k++) {
        float zv = zb[w][k];
        t0 += wp[lane * 49 + k] * zv;
        t1 += wp[(lane + 32) * 49 + k] * zv;
    }
    t0 = fmaxf(t0, 0.f);
    t1 = fmaxf(t1, 0.f);
    g_t[(size_t)n * 64 + lane]      = t0;
    g_t[(size_t)n * 64 + lane + 32] = t1;

    #pragma unroll
    for (int hd = 0; hd < 4; hd++) {
        float ps = t0 * g_wsrc[hd * 64 + lane] + t1 * g_wsrc[hd * 64 + 32 + lane];
        float pd = t0 * g_wdst[hd * 64 + lane] + t1 * g_wdst[hd * 64 + 32 + lane];
        float vs = warp_sum(ps);
        float vd = warp_sum(pd);
        if (lane == 0) { g_asrc[n * 4 + hd] = vs; g_adst[n * 4 + hd] = vd; }
    }
}

// --------- fused softmax + aggregation in t-space: warp per dst node --------
__global__ void k_agg() {
    int tid = threadIdx.x;
    int w = tid >> 5, lane = tid & 31;
    int n = blockIdx.x * 8 + w;
    int r0 = g_rowptr[n], r1 = g_rowptr[n + 1];
    float4 ad = *(const float4*)&g_adst[n * 4];

    float acc[8];
    #pragma unroll
    for (int i = 0; i < 8; i++) acc[i] = 0.f;
    float s0 = 0.f, s1 = 0.f, s2 = 0.f, s3 = 0.f;

    for (int base = r0; base < r1; base += 32) {
        int cnt = min(32, r1 - base);
        int si = 0;
        float ex0 = 0.f, ex1 = 0.f, ex2 = 0.f, ex3 = 0.f;
        if (lane < cnt) {
            si = g_col[base + lane];
            float4 as = *(const float4*)&g_asrc[si * 4];
            float e0 = as.x + ad.x, e1 = as.y + ad.y, e2 = as.z + ad.z, e3 = as.w + ad.w;
            e0 = e0 > 0.f ? e0 : 0.2f * e0;
            e1 = e1 > 0.f ? e1 : 0.2f * e1;
            e2 = e2 > 0.f ? e2 : 0.2f * e2;
            e3 = e3 > 0.f ? e3 : 0.2f * e3;
            ex0 = expf(e0); ex1 = expf(e1); ex2 = expf(e2); ex3 = expf(e3);
            s0 += ex0; s1 += ex1; s2 += ex2; s3 += ex3;
        }
        for (int j = 0; j < cnt; j++) {
            int sj   = __shfl_sync(0xffffffffu, si, j);
            float a0 = __shfl_sync(0xffffffffu, ex0, j);
            float a1 = __shfl_sync(0xffffffffu, ex1, j);
            float a2 = __shfl_sync(0xffffffffu, ex2, j);
            float a3 = __shfl_sync(0xffffffffu, ex3, j);
            const float* tr = g_t + (size_t)sj * 64;
            float u0 = tr[lane], u1 = tr[lane + 32];
            acc[0] += a0 * u0; acc[1] += a0 * u1;
            acc[2] += a1 * u0; acc[3] += a1 * u1;
            acc[4] += a2 * u0; acc[5] += a2 * u1;
            acc[6] += a3 * u0; acc[7] += a3 * u1;
        }
    }
    s0 = warp_sum(s0); s1 = warp_sum(s1); s2 = warp_sum(s2); s3 = warp_sum(s3);
    float i0 = 1.f / fmaxf(s0, 1e-16f);
    float i1 = 1.f / fmaxf(s1, 1e-16f);
    float i2 = 1.f / fmaxf(s2, 1e-16f);
    float i3 = 1.f / fmaxf(s3, 1e-16f);
    float* o = g_aggt + (size_t)n * 256;
    o[lane]            = acc[0] * i0;  o[lane + 32]       = acc[1] * i0;
    o[64 + lane]       = acc[2] * i1;  o[64 + 32 + lane]  = acc[3] * i1;
    o[128 + lane]      = acc[4] * i2;  o[128 + 32 + lane] = acc[5] * i2;
    o[192 + lane]      = acc[6] * i3;  o[192 + 32 + lane] = acc[7] * i3;
}

// -------- GEMM: out[:, hd] = aggt[:, hd] @ Wg[hd]^T, plus bn3 stats ----------
__global__ void k_gemm_out(const float* __restrict__ Wg) {
    __shared__ float tsh[64 * 68];
    __shared__ float wsh[64 * 68];
    int n0 = blockIdx.x * 64;
    int hd = blockIdx.y;
    int out0 = hd * 64;
    int tid = threadIdx.x;

    for (int i = tid; i < 64 * 16; i += 256) {
        int r = i >> 4, c = (i & 15) << 2;
        float4 v = make_float4(0.f, 0.f, 0.f, 0.f);
        int n = n0 + r;
        if (n < Nn) v = *(const float4*)&g_aggt[(size_t)n * 256 + out0 + c];
        *(float4*)&tsh[r * 68 + c] = v;
        float4 wv = *(const float4*)&Wg[(size_t)(out0 + r) * 64 + c];
        *(float4*)&wsh[r * 68 + c] = wv;
    }
    __syncthreads();

    int tx = tid & 31, ty = tid >> 5;
    float acc[8][2];
    #pragma unroll
    for (int i = 0; i < 8; i++) { acc[i][0] = 0.f; acc[i][1] = 0.f; }

    #pragma unroll 4
    for (int k = 0; k < 64; k += 4) {
        float4 tv[8], wv[2];
        #pragma unroll
        for (int i = 0; i < 8; i++) tv[i] = *(float4*)&tsh[(ty * 8 + i) * 68 + k];
        wv[0] = *(float4*)&wsh[tx * 68 + k];
        wv[1] = *(float4*)&wsh[(tx + 32) * 68 + k];
        #pragma unroll
        for (int i = 0; i < 8; i++) {
            #pragma unroll
            for (int o = 0; o < 2; o++) {
                acc[i][o] += tv[i].x * wv[o].x;
                acc[i][o] += tv[i].y * wv[o].y;
                acc[i][o] += tv[i].z * wv[o].z;
                acc[i][o] += tv[i].w * wv[o].w;
            }
        }
    }
    float ps0 = 0.f, pq0 = 0.f, ps1 = 0.f, pq1 = 0.f;
    #pragma unroll
    for (int i = 0; i < 8; i++) {
        int n = n0 + ty * 8 + i;
        if (n < Nn) {
            g_out[(size_t)n * 256 + out0 + tx]      = acc[i][0];
            g_out[(size_t)n * 256 + out0 + tx + 32] = acc[i][1];
            ps0 += acc[i][0]; pq0 += acc[i][0] * acc[i][0];
            ps1 += acc[i][1]; pq1 += acc[i][1] * acc[i][1];
        }
    }
    atomicAdd(&g_sum3[out0 + tx], ps0);
    atomicAdd(&g_sumsq3[out0 + tx], pq0);
    atomicAdd(&g_sum3[out0 + tx + 32], ps1);
    atomicAdd(&g_sumsq3[out0 + tx + 32], pq1);
}

// --------------- bn3 (inline finalize) + elu + graph pooling -----------------
__global__ void k_pool(const int* __restrict__ batch,
                       const float* __restrict__ bn3_g, const float* __restrict__ bn3_b) {
    int n = blockIdx.x, c = threadIdx.x;
    const float invN = 1.f / Nn;
    float mean = g_sum3[c] * invN;
    float var  = g_sumsq3[c] * invN - mean * mean;
    float r = rsqrtf(var + EPS);
    float sc = r * bn3_g[c];
    float sh = bn3_b[c] - mean * sc;
    int b = batch[n];
    float v = g_out[(size_t)n * 256 + c] * sc + sh;
    v = v > 0.f ? v : (expf(v) - 1.f);
    atomicAdd(&g_pooled[b * 256 + c], v);
    if (c == 0) atomicAdd(&g_cnt[b], 1.f);
}

// ------------------------- head MLP ------------------------------------------
__global__ void k_head(const float* __restrict__ W1, const float* __restrict__ b1,
                       const float* __restrict__ W2, const float* __restrict__ b2,
                       float* __restrict__ out) {
    __shared__ float p[256];
    __shared__ float hm[64];
    int g = blockIdx.x, t = threadIdx.x;
    float cnt = fmaxf(g_cnt[g], 1.f);
    p[t] = g_pooled[g * 256 + t] / cnt;
    __syncthreads();
    if (t < 64) {
        float a = b1[t];
        #pragma unroll 8
        for (int c = 0; c < 256; c++) a += p[c] * W1[t * 256 + c];
        hm[t] = fmaxf(a, 0.f);
    }
    __syncthreads();
    if (t < 2) {
        float a = b2[t];
        #pragma unroll
        for (int k = 0; k < 64; k++) a += hm[k] * W2[t * 64 + k];
        out[g * 2 + t] = a;
    }
}

// ------------------------- launch ---------------------------------------------
extern "C" void kernel_launch(void* const* d_in, const int* in_sizes, int n_in,
                              void* d_out, int out_size) {
    const float* x       = (const float*)d_in[0];
    const int*   ei      = (const int*)d_in[1];
    const int*   batch   = (const int*)d_in[2];
    const float* ln_g    = (const float*)d_in[3];
    const float* ln_b    = (const float*)d_in[4];
    const float* bn1_g   = (const float*)d_in[5];
    const float* bn1_b   = (const float*)d_in[6];
    const float* Wc      = (const float*)d_in[7];
    const float* bc      = (const float*)d_in[8];
    const float* bn2_g   = (const float*)d_in[9];
    const float* bn2_b   = (const float*)d_in[10];
    const float* Wp      = (const float*)d_in[11];
    const float* bp      = (const float*)d_in[12];
    const float* Wg      = (const float*)d_in[13];
    const float* att_src = (const float*)d_in[14];
    const float* att_dst = (const float*)d_in[15];
    // d_in[16] = bg : cancels under bn3 (pure mean shift) -> unused
    const float* bn3_g   = (const float*)d_in[17];
    const float* bn3_b   = (const float*)d_in[18];
    const float* W1      = (const float*)d_in[19];
    const float* b1      = (const float*)d_in[20];
    const float* W2      = (const float*)d_in[21];
    const float* b2      = (const float*)d_in[22];
    float* out = (float*)d_out;

    k_init<<<576, 256>>>();
    k_pre<<<1000 + (Ee + 511) / 512, 512>>>(x, ei);
    k_fold_wc<<<16, 512>>>(Wc, bc, bn1_g, bn1_b);
    k_scan1<<<NCHUNK, 256>>>();
    k_scan2<<<1, 256>>>();
    k_scan3<<<NCHUNK, 256>>>();
    k_scatter<<<3125, 256>>>(ei);
    k_node_z<<<6250, 256>>>(x, ln_g, ln_b);
    k_fold2<<<68, 64>>>(Wp, bp, bn2_g, bn2_b, Wg, att_src, att_dst);
    k_node_t<<<6250, 256>>>();
    k_agg<<<6250, 256>>>();
    dim3 gh(782, 4);
    k_gemm_out<<<gh, 256>>>(Wg);
    k_pool<<<Nn, 256>>>(batch, bn3_g, bn3_b);
    k_head<<<Gg, 256>>>(W1, b1, W2, b2, out);
}

// round 6
// speedup vs baseline: 1.9347x; 1.2417x over previous
#include <cuda_runtime.h>
#include <math.h>
#include <stdint.h>

#define Nn 50000
#define Ee 800000
#define Gg 512
#define EPS 1e-5f
#define NCH 98            // ceil(50000/512) chunks for scan
#define B_STATS 1000
#define B_DEG   1563      // ceil(800000/512)
#define B_BP    98        // ceil(50000/512)

// ------------------------- device scratch (static, no allocs) ---------------
__device__ float g_sum1[512], g_sumsq1[512];
__device__ __align__(16) float g_Wc2[16 * 512];
__device__ float g_bc2[16];
__device__ __align__(16) float g_z[(size_t)Nn * 48];
__device__ float g_sum2[48], g_sumsq2[48];
__device__ float g_Wp2[64 * 48], g_bp2[64];
__device__ __align__(16) float g_t[(size_t)Nn * 64];
__device__ float g_wsrc[4 * 64], g_wdst[4 * 64];
__device__ __align__(16) float g_asrc[Nn * 4];
__device__ __align__(16) float g_adst[Nn * 4];
__device__ int g_deg[Nn];
__device__ int g_rowptr[Nn + 1];
__device__ int g_cursor[Nn];
__device__ int g_chunksum[NCH];
__device__ int g_chunkoff[NCH];
__device__ int g_col[Ee];
__device__ int g_gptr[Gg + 1];
__device__ __align__(16) float g_aggt[(size_t)Nn * 256];
__device__ __align__(16) float g_out[(size_t)Nn * 256];
__device__ float g_sum3[256], g_sumsq3[256];

// ------------------------- helpers ------------------------------------------
__device__ __forceinline__ float warp_sum(float v) {
    #pragma unroll
    for (int off = 16; off; off >>= 1) v += __shfl_xor_sync(0xffffffffu, v, off);
    return v;
}
__device__ __forceinline__ int warp_sum_i(int v) {
    #pragma unroll
    for (int off = 16; off; off >>= 1) v += __shfl_xor_sync(0xffffffffu, v, off);
    return v;
}

// ------------------------- init (per-launch reset; graph-replay safe) -------
__global__ void k_init() {
    int i = blockIdx.x * blockDim.x + threadIdx.x;
    int stride = gridDim.x * blockDim.x;
    for (int j = i; j < Nn; j += stride) g_deg[j] = 0;
    if (i < 512) { g_sum1[i] = 0.f; g_sumsq1[i] = 0.f; }
    if (i < 256) { g_sum3[i] = 0.f; g_sumsq3[i] = 0.f; }
    if (i < 48)  { g_sum2[i] = 0.f; g_sumsq2[i] = 0.f; }
}

// ---- merged: bn1 stats | degree count | batch group boundaries --------------
__global__ void k_pre(const float* __restrict__ x, const int* __restrict__ ei,
                      const int* __restrict__ batch) {
    int b = blockIdx.x;
    if (b < B_STATS) {
        int c = threadIdx.x;  // 512 threads
        float s = 0.f, q = 0.f;
        for (int r = b; r < Nn; r += B_STATS) {
            float v = x[(size_t)r * 544 + c];
            s += v; q += v * v;
        }
        atomicAdd(&g_sum1[c], s);
        atomicAdd(&g_sumsq1[c], q);
    } else if (b < B_STATS + B_DEG) {
        int e = (b - B_STATS) * 512 + threadIdx.x;
        if (e < Ee) atomicAdd(&g_deg[ei[Ee + e]], 1);
    } else {
        int n = (b - B_STATS - B_DEG) * 512 + threadIdx.x;
        if (n < Nn) {
            int bb = batch[n];
            int prev = (n == 0) ? -1 : batch[n - 1];
            for (int g = prev + 1; g <= bb; g++) g_gptr[g] = n;
            if (n == Nn - 1) for (int g = bb + 1; g <= Gg; g++) g_gptr[g] = Nn;
        }
    }
}

// ---- merged: fold bn1 into Wc (blocks 0..15) | scan phase 1 (blocks 16..113)
__global__ void k_fold_scan1(const float* __restrict__ Wc, const float* __restrict__ bc,
                             const float* __restrict__ bn1_g, const float* __restrict__ bn1_b) {
    int b = blockIdx.x, t = threadIdx.x;  // 512 threads
    if (b < 16) {
        __shared__ float red[512];
        const float invN = 1.f / Nn;
        float mean = g_sum1[t] * invN;
        float var  = g_sumsq1[t] * invN - mean * mean;
        float r = rsqrtf(var + EPS);
        float sc = r * bn1_g[t];
        float sh = bn1_b[t] - mean * sc;
        float w = Wc[b * 512 + t];
        g_Wc2[b * 512 + t] = w * sc;
        red[t] = w * sh;
        __syncthreads();
        for (int s = 256; s; s >>= 1) { if (t < s) red[t] += red[t + s]; __syncthreads(); }
        if (t == 0) g_bc2[b] = bc[b] + red[0];
    } else {
        int chunk = b - 16;
        int idx = chunk * 512 + t;
        int d = (idx < Nn) ? g_deg[idx] : 0;
        int s = warp_sum_i(d);
        __shared__ int sh[16];
        if ((t & 31) == 0) sh[t >> 5] = s;
        __syncthreads();
        if (t < 16) {
            int v = sh[t];
            #pragma unroll
            for (int off = 8; off; off >>= 1) v += __shfl_xor_sync(0xffffu, v, off);
            if (t == 0) g_chunksum[chunk] = v;
        }
    }
}

__global__ void k_scan2() {   // 1 block x 128: exclusive scan of 98 chunk sums
    __shared__ int sh[128];
    int t = threadIdx.x;
    int v = (t < NCH) ? g_chunksum[t] : 0;
    sh[t] = v;
    __syncthreads();
    for (int off = 1; off < 128; off <<= 1) {
        int u = (t >= off) ? sh[t - off] : 0;
        __syncthreads();
        sh[t] += u;
        __syncthreads();
    }
    if (t < NCH) g_chunkoff[t] = sh[t] - v;
}

// ---- merged: scan phase 3 (blocks 0..97) | node_z (blocks 98..3222) --------
__global__ void k_scan3_nodez(const float* __restrict__ x,
                              const float* __restrict__ ln_g, const float* __restrict__ ln_b) {
    int b = blockIdx.x, tid = threadIdx.x;  // 512 threads
    if (b < NCH) {
        __shared__ int sh[512];
        int idx = b * 512 + tid;
        int d = (idx < Nn) ? g_deg[idx] : 0;
        sh[tid] = d;
        __syncthreads();
        for (int off = 1; off < 512; off <<= 1) {
            int u = (tid >= off) ? sh[tid - off] : 0;
            __syncthreads();
            sh[tid] += u;
            __syncthreads();
        }
        if (idx < Nn) {
            int pos = g_chunkoff[b] + sh[tid] - d;
            g_rowptr[idx] = pos;
            g_cursor[idx] = pos;
        }
        if (idx == Nn - 1) g_rowptr[Nn] = Ee;
    } else {
        __shared__ float sh_s[48], sh_q[48];
        if (tid < 48) { sh_s[tid] = 0.f; sh_q[tid] = 0.f; }
        __syncthreads();
        int w = tid >> 5, lane = tid & 31;
        int n = (b - NCH) * 16 + w;   // 3125 blocks x 16 warps = 50000
        const float* row = x + (size_t)n * 544;

        float fv = row[512 + lane];
        float mu = warp_sum(fv) * (1.f / 32.f);
        float qq = warp_sum(fv * fv) * (1.f / 32.f);
        float fr = rsqrtf(qq - mu * mu + EPS);
        float fn = (fv - mu) * fr * ln_g[lane] + ln_b[lane];

        float4 xv[4];
        #pragma unroll
        for (int i = 0; i < 4; i++)
            xv[i] = *(const float4*)&row[4 * lane + 128 * i];

        float xc = 0.f;
        #pragma unroll
        for (int o = 0; o < 16; o++) {
            float a = 0.f;
            #pragma unroll
            for (int i = 0; i < 4; i++) {
                float4 wv = *(const float4*)&g_Wc2[o * 512 + 4 * lane + 128 * i];
                a += xv[i].x * wv.x + xv[i].y * wv.y + xv[i].z * wv.z + xv[i].w * wv.w;
            }
            float v = warp_sum(a);
            if (lane == o) xc = v + g_bc2[o];
        }

        float* zr = g_z + (size_t)n * 48;
        if (lane < 16) zr[lane] = xc;
        zr[16 + lane] = fn;

        if (lane < 16) { atomicAdd(&sh_s[lane], xc); atomicAdd(&sh_q[lane], xc * xc); }
        atomicAdd(&sh_s[16 + lane], fn);
        atomicAdd(&sh_q[16 + lane], fn * fn);
        __syncthreads();
        if (tid < 48) { atomicAdd(&g_sum2[tid], sh_s[tid]); atomicAdd(&g_sumsq2[tid], sh_q[tid]); }
    }
}

// ---- merged: fold bn2/att (blocks 0..67) | CSR scatter (blocks 68+) ---------
__global__ void k_fold2_scatter(const float* __restrict__ Wp, const float* __restrict__ bp,
                                const float* __restrict__ bn2_g, const float* __restrict__ bn2_b,
                                const float* __restrict__ Wg,
                                const float* __restrict__ att_src, const float* __restrict__ att_dst,
                                const int* __restrict__ ei) {
    int b = blockIdx.x, t = threadIdx.x;  // 256 threads
    if (b < 64) {
        __shared__ float red[256];
        float p = 0.f;
        if (t < 48) {
            const float invN = 1.f / Nn;
            float mean = g_sum2[t] * invN;
            float var  = g_sumsq2[t] * invN - mean * mean;
            float r = rsqrtf(var + EPS);
            float sc = r * bn2_g[t];
            float sh = bn2_b[t] - mean * sc;
            float w = Wp[b * 48 + t];
            g_Wp2[b * 48 + t] = w * sc;
            p = w * sh;
        }
        red[t] = p;
        __syncthreads();
        for (int s = 128; s; s >>= 1) { if (t < s) red[t] += red[t + s]; __syncthreads(); }
        if (t == 0) g_bp2[b] = bp[b] + red[0];
    } else if (b < 68) {
        int hd = b - 64;
        __shared__ float as[64], ad[64];
        if (t < 64) { as[t] = att_src[hd * 64 + t]; ad[t] = att_dst[hd * 64 + t]; }
        __syncthreads();
        if (t < 64) {
            float s = 0.f, d = 0.f;
            #pragma unroll 8
            for (int j = 0; j < 64; j++) {
                float w = Wg[(size_t)(hd * 64 + j) * 64 + t];
                s += as[j] * w;
                d += ad[j] * w;
            }
            g_wsrc[hd * 64 + t] = s;
            g_wdst[hd * 64 + t] = d;
        }
    } else {
        int e = (b - 68) * 256 + t;
        int di = ei[Ee + e];
        int pos = atomicAdd(&g_cursor[di], 1);
        g_col[pos] = ei[e];
    }
}

// --------------- per node: t = relu(Wp2 z + bp2), plus attention logits -----
__global__ void k_node_t() {
    __shared__ float wp[64 * 49];
    __shared__ float zb[8][48];
    int tid = threadIdx.x;
    for (int i = tid; i < 64 * 48; i += 256) {
        int o = i / 48, k = i - o * 48;
        wp[o * 49 + k] = g_Wp2[i];
    }
    __syncthreads();
    int w = tid >> 5, lane = tid & 31;
    int n = blockIdx.x * 8 + w;
    const float* zr = g_z + (size_t)n * 48;
    zb[w][lane] = zr[lane];
    if (lane < 16) zb[w][32 + lane] = zr[32 + lane];
    __syncwarp();
    float t0 = g_bp2[lane], t1 = g_bp2[lane + 32];
    #pragma unroll
    for (int k = 0; k < 48; k++) {
        float zv = zb[w][k];
        t0 += wp[lane * 49 + k] * zv;
        t1 += wp[(lane + 32) * 49 + k] * zv;
    }
    t0 = fmaxf(t0, 0.f);
    t1 = fmaxf(t1, 0.f);
    g_t[(size_t)n * 64 + lane]      = t0;
    g_t[(size_t)n * 64 + lane + 32] = t1;

    #pragma unroll
    for (int hd = 0; hd < 4; hd++) {
        float ps = t0 * g_wsrc[hd * 64 + lane] + t1 * g_wsrc[hd * 64 + 32 + lane];
        float pd = t0 * g_wdst[hd * 64 + lane] + t1 * g_wdst[hd * 64 + 32 + lane];
        float vs = warp_sum(ps);
        float vd = warp_sum(pd);
        if (lane == 0) { g_asrc[n * 4 + hd] = vs; g_adst[n * 4 + hd] = vd; }
    }
}

// --------- fused softmax + aggregation in t-space: warp per dst node --------
__global__ void k_agg() {
    int tid = threadIdx.x;
    int w = tid >> 5, lane = tid & 31;
    int n = blockIdx.x * 8 + w;
    int r0 = g_rowptr[n], r1 = g_rowptr[n + 1];
    float4 ad = *(const float4*)&g_adst[n * 4];

    float acc[8];
    #pragma unroll
    for (int i = 0; i < 8; i++) acc[i] = 0.f;
    float s0 = 0.f, s1 = 0.f, s2 = 0.f, s3 = 0.f;

    for (int base = r0; base < r1; base += 32) {
        int cnt = min(32, r1 - base);
        int si = 0;
        float ex0 = 0.f, ex1 = 0.f, ex2 = 0.f, ex3 = 0.f;
        if (lane < cnt) {
            si = g_col[base + lane];
            float4 as = *(const float4*)&g_asrc[si * 4];
            float e0 = as.x + ad.x, e1 = as.y + ad.y, e2 = as.z + ad.z, e3 = as.w + ad.w;
            e0 = e0 > 0.f ? e0 : 0.2f * e0;
            e1 = e1 > 0.f ? e1 : 0.2f * e1;
            e2 = e2 > 0.f ? e2 : 0.2f * e2;
            e3 = e3 > 0.f ? e3 : 0.2f * e3;
            ex0 = expf(e0); ex1 = expf(e1); ex2 = expf(e2); ex3 = expf(e3);
            s0 += ex0; s1 += ex1; s2 += ex2; s3 += ex3;
        }
        for (int j = 0; j < cnt; j++) {
            int sj   = __shfl_sync(0xffffffffu, si, j);
            float a0 = __shfl_sync(0xffffffffu, ex0, j);
            float a1 = __shfl_sync(0xffffffffu, ex1, j);
            float a2 = __shfl_sync(0xffffffffu, ex2, j);
            float a3 = __shfl_sync(0xffffffffu, ex3, j);
            const float* tr = g_t + (size_t)sj * 64;
            float u0 = tr[lane], u1 = tr[lane + 32];
            acc[0] += a0 * u0; acc[1] += a0 * u1;
            acc[2] += a1 * u0; acc[3] += a1 * u1;
            acc[4] += a2 * u0; acc[5] += a2 * u1;
            acc[6] += a3 * u0; acc[7] += a3 * u1;
        }
    }
    s0 = warp_sum(s0); s1 = warp_sum(s1); s2 = warp_sum(s2); s3 = warp_sum(s3);
    float i0 = 1.f / fmaxf(s0, 1e-16f);
    float i1 = 1.f / fmaxf(s1, 1e-16f);
    float i2 = 1.f / fmaxf(s2, 1e-16f);
    float i3 = 1.f / fmaxf(s3, 1e-16f);
    float* o = g_aggt + (size_t)n * 256;
    o[lane]            = acc[0] * i0;  o[lane + 32]       = acc[1] * i0;
    o[64 + lane]       = acc[2] * i1;  o[64 + 32 + lane]  = acc[3] * i1;
    o[128 + lane]      = acc[4] * i2;  o[128 + 32 + lane] = acc[5] * i2;
    o[192 + lane]      = acc[6] * i3;  o[192 + 32 + lane] = acc[7] * i3;
}

// -------- GEMM: out[:, hd] = aggt[:, hd] @ Wg[hd]^T + reduced bn3 stats ------
__global__ void k_gemm_out(const float* __restrict__ Wg) {
    __shared__ float tsh[64 * 68];
    __shared__ float wsh[64 * 68];
    int n0 = blockIdx.x * 64;
    int hd = blockIdx.y;
    int out0 = hd * 64;
    int tid = threadIdx.x;

    for (int i = tid; i < 64 * 16; i += 256) {
        int r = i >> 4, c = (i & 15) << 2;
        float4 v = make_float4(0.f, 0.f, 0.f, 0.f);
        int n = n0 + r;
        if (n < Nn) v = *(const float4*)&g_aggt[(size_t)n * 256 + out0 + c];
        *(float4*)&tsh[r * 68 + c] = v;
        float4 wv = *(const float4*)&Wg[(size_t)(out0 + r) * 64 + c];
        *(float4*)&wsh[r * 68 + c] = wv;
    }
    __syncthreads();

    int tx = tid & 31, ty = tid >> 5;
    float acc[8][2];
    #pragma unroll
    for (int i = 0; i < 8; i++) { acc[i][0] = 0.f; acc[i][1] = 0.f; }

    #pragma unroll 4
    for (int k = 0; k < 64; k += 4) {
        float4 tv[8], wv[2];
        #pragma unroll
        for (int i = 0; i < 8; i++) tv[i] = *(float4*)&tsh[(ty * 8 + i) * 68 + k];
        wv[0] = *(float4*)&wsh[tx * 68 + k];
        wv[1] = *(float4*)&wsh[(tx + 32) * 68 + k];
        #pragma unroll
        for (int i = 0; i < 8; i++) {
            #pragma unroll
            for (int o = 0; o < 2; o++) {
                acc[i][o] += tv[i].x * wv[o].x;
                acc[i][o] += tv[i].y * wv[o].y;
                acc[i][o] += tv[i].z * wv[o].z;
                acc[i][o] += tv[i].w * wv[o].w;
            }
        }
    }
    float ps0 = 0.f, pq0 = 0.f, ps1 = 0.f, pq1 = 0.f;
    #pragma unroll
    for (int i = 0; i < 8; i++) {
        int n = n0 + ty * 8 + i;
        if (n < Nn) {
            g_out[(size_t)n * 256 + out0 + tx]      = acc[i][0];
            g_out[(size_t)n * 256 + out0 + tx + 32] = acc[i][1];
            ps0 += acc[i][0]; pq0 += acc[i][0] * acc[i][0];
            ps1 += acc[i][1]; pq1 += acc[i][1] * acc[i][1];
        }
    }
    // cross-warp reduce stats in smem, then 32 threads do the atomics
    __syncthreads();
    tsh[ty * 32 + tx]       = ps0;
    tsh[256 + ty * 32 + tx] = pq0;
    tsh[512 + ty * 32 + tx] = ps1;
    tsh[768 + ty * 32 + tx] = pq1;
    __syncthreads();
    if (ty == 0) {
        float a0 = 0.f, a1 = 0.f, a2 = 0.f, a3 = 0.f;
        #pragma unroll
        for (int j = 0; j < 8; j++) {
            a0 += tsh[j * 32 + tx];
            a1 += tsh[256 + j * 32 + tx];
            a2 += tsh[512 + j * 32 + tx];
            a3 += tsh[768 + j * 32 + tx];
        }
        atomicAdd(&g_sum3[out0 + tx], a0);
        atomicAdd(&g_sumsq3[out0 + tx], a1);
        atomicAdd(&g_sum3[out0 + tx + 32], a2);
        atomicAdd(&g_sumsq3[out0 + tx + 32], a3);
    }
}

// -------- per-group: bn3 + elu + mean-pool (contiguous, no atomics) + head --
__global__ void k_pool_head(const float* __restrict__ bn3_g, const float* __restrict__ bn3_b,
                            const float* __restrict__ W1, const float* __restrict__ b1,
                            const float* __restrict__ W2, const float* __restrict__ b2,
                            float* __restrict__ out) {
    __shared__ float p[256];
    __shared__ float hm[64];
    int g = blockIdx.x, c = threadIdx.x;
    const float invN = 1.f / Nn;
    float mean = g_sum3[c] * invN;
    float var  = g_sumsq3[c] * invN - mean * mean;
    float r = rsqrtf(var + EPS);
    float sc = r * bn3_g[c];
    float sh = bn3_b[c] - mean * sc;
    int r0 = g_gptr[g], r1 = g_gptr[g + 1];
    float s = 0.f;
    for (int n = r0; n < r1; n++) {
        float v = g_out[(size_t)n * 256 + c] * sc + sh;
        v = v > 0.f ? v : (expf(v) - 1.f);
        s += v;
    }
    p[c] = s / fmaxf((float)(r1 - r0), 1.f);
    __syncthreads();
    if (c < 64) {
        float a = b1[c];
        #pragma unroll 8
        for (int k = 0; k < 256; k++) a += p[k] * W1[c * 256 + k];
        hm[c] = fmaxf(a, 0.f);
    }
    __syncthreads();
    if (c < 2) {
        float a = b2[c];
        #pragma unroll
        for (int k = 0; k < 64; k++) a += hm[k] * W2[c * 64 + k];
        out[g * 2 + c] = a;
    }
}

// ------------------------- launch ---------------------------------------------
extern "C" void kernel_launch(void* const* d_in, const int* in_sizes, int n_in,
                              void* d_out, int out_size) {
    const float* x       = (const float*)d_in[0];
    const int*   ei      = (const int*)d_in[1];
    const int*   batch   = (const int*)d_in[2];
    const float* ln_g    = (const float*)d_in[3];
    const float* ln_b    = (const float*)d_in[4];
    const float* bn1_g   = (const float*)d_in[5];
    const float* bn1_b   = (const float*)d_in[6];
    const float* Wc      = (const float*)d_in[7];
    const float* bc      = (const float*)d_in[8];
    const float* bn2_g   = (const float*)d_in[9];
    const float* bn2_b   = (const float*)d_in[10];
    const float* Wp      = (const float*)d_in[11];
    const float* bp      = (const float*)d_in[12];
    const float* Wg      = (const float*)d_in[13];
    const float* att_src = (const float*)d_in[14];
    const float* att_dst = (const float*)d_in[15];
    // d_in[16] = bg : cancels under bn3 (pure mean shift) -> unused
    const float* bn3_g   = (const float*)d_in[17];
    const float* bn3_b   = (const float*)d_in[18];
    const float* W1      = (const float*)d_in[19];
    const float* b1      = (const float*)d_in[20];
    const float* W2      = (const float*)d_in[21];
    const float* b2      = (const float*)d_in[22];
    float* out = (float*)d_out;

    k_init<<<196, 256>>>();
    k_pre<<<B_STATS + B_DEG + B_BP, 512>>>(x, ei, batch);
    k_fold_scan1<<<16 + NCH, 512>>>(Wc, bc, bn1_g, bn1_b);
    k_scan2<<<1, 128>>>();
    k_scan3_nodez<<<NCH + 3125, 512>>>(x, ln_g, ln_b);
    k_fold2_scatter<<<68 + 3125, 256>>>(Wp, bp, bn2_g, bn2_b, Wg, att_src, att_dst, ei);
    k_node_t<<<6250, 256>>>();
    k_agg<<<6250, 256>>>();
    dim3 gh(782, 4);
    k_gemm_out<<<gh, 256>>>(Wg);
    k_pool_head<<<Gg, 256>>>(bn3_g, bn3_b, W1, b1, W2, b2, out);
}